// round 5
// baseline (speedup 1.0000x reference)
#include <cuda_runtime.h>
#include <cuda_bf16.h>
#include <mma.h>
#include <math.h>
#include <stdint.h>

using namespace nvcuda;

#define NN 100000
#define NE 1600000
#define NB 256
#define HD 128
#define NL 3

#define TR 32
#define NT (NN / TR)          // 3125 exact
#define NBLK 148
#define LDA 136               // bf16 smem stride
#define LDSG 132              // f32 staging stride
#define WTILE_B (128 * LDA * 2)   // 34816 bytes per 128x136 bf16 weight tile

// smem map for fgemm
#define SM_ABUF 0                         // 2 buffers x (hi 8704 + lo 8704) = 34816
#define SM_W    34816                     // 4 tiles = 139264
#define SM_STG  (34816 + 139264)          // 32*132*4 = 16896
#define FG_SMEM (SM_STG + TR * LDSG * 4)  // 190976

// ---------------- device scratch ----------------
__device__ __align__(16) __nv_bfloat16 g_ahi[NN * HD];
__device__ __align__(16) __nv_bfloat16 g_alo[NN * HD];
__device__ float g_z2[NN * HD];
__device__ int   g_rowptr[NN + 1];
__device__ int   g_fill[NN];
__device__ int   g_colsrc[NE];
__device__ float g_stats[2 * HD];
__device__ float g_scale[HD];
__device__ float g_shift[HD];
__device__ float g_graph[NB * 3 * HD];
__device__ int   g_start[NB + 1];
__device__ __align__(16) __nv_bfloat16 g_wimg[NL * 4 * 128 * LDA];

union B8 { uint4 u; __nv_bfloat16 b[8]; };
union B4 { unsigned long long u; __nv_bfloat16 b[4]; };

__device__ __forceinline__ uint32_t smem_u32(const void* p) {
    uint32_t a;
    asm("{ .reg .u64 t; cvta.to.shared.u64 t, %1; cvt.u32.u64 %0, t; }" : "=r"(a) : "l"(p));
    return a;
}
__device__ __forceinline__ void cp16(uint32_t dst, const void* src) {
    asm volatile("cp.async.cg.shared.global [%0], [%1], 16;" :: "r"(dst), "l"(src));
}
__device__ __forceinline__ void cp_commit() { asm volatile("cp.async.commit_group;"); }
__device__ __forceinline__ void cp_wait0()  { asm volatile("cp.async.wait_group 0;"); }

// ---------------- init / weight prep ----------------
__global__ void k_zero() {
    int i = blockIdx.x * blockDim.x + threadIdx.x;
    if (i <= NN) g_rowptr[i] = 0;
    if (i < NN)  g_fill[i] = 0;
    if (i < 2 * HD) g_stats[i] = 0.f;
}

__global__ void k_prepw(const float* __restrict__ gW1, const float* __restrict__ gW2) {
    int idx = blockIdx.x * blockDim.x + threadIdx.x;
    if (idx >= NL * 2 * 16384) return;
    int l = idx / 32768;
    int rem = idx - l * 32768;
    int m = rem >> 14;
    int e = rem & 16383;
    int k = e >> 7;
    int n = e & 127;
    float v = (m ? gW2 : gW1)[l * 16384 + k * 128 + n];
    __nv_bfloat16 hi = __float2bfloat16_rn(v);
    __nv_bfloat16 lo = __float2bfloat16_rn(v - __bfloat162float(hi));
    __nv_bfloat16* base = g_wimg + (size_t)(l * 4 + m * 2) * 128 * LDA;
    base[k * LDA + n] = hi;
    base[128 * LDA + k * LDA + n] = lo;
}

// ---------------- CSR build ----------------
__global__ void k_hist(const int* __restrict__ ei) {
    int e = blockIdx.x * blockDim.x + threadIdx.x;
    if (e < NE) atomicAdd(&g_rowptr[ei[NE + e] + 1], 1);
}

__global__ void k_scan() {
    __shared__ int wsum[32];
    __shared__ int carry;
    int tid = threadIdx.x, lane = tid & 31, wid = tid >> 5;
    if (tid == 0) carry = 0;
    const int NCH = (NN + 1 + 1023) / 1024;
    int nv = g_rowptr[tid];
    __syncthreads();
    for (int ch = 0; ch < NCH; ch++) {
        int v = nv;
        if (ch + 1 < NCH) {
            int gn = (ch + 1) * 1024 + tid;
            nv = (gn <= NN) ? g_rowptr[gn] : 0;
        }
        int x = v;
#pragma unroll
        for (int d = 1; d < 32; d <<= 1) { int y = __shfl_up_sync(0xFFFFFFFFu, x, d); if (lane >= d) x += y; }
        if (lane == 31) wsum[wid] = x;
        __syncthreads();
        if (wid == 0) {
            int y = wsum[lane];
#pragma unroll
            for (int d = 1; d < 32; d <<= 1) { int z = __shfl_up_sync(0xFFFFFFFFu, y, d); if (lane >= d) y += z; }
            wsum[lane] = y;
        }
        __syncthreads();
        if (wid > 0) x += wsum[wid - 1];
        int out = x + carry;
        int gid = ch * 1024 + tid;
        if (gid <= NN) g_rowptr[gid] = out;
        __syncthreads();
        if (tid == 1023) carry = out;
        __syncthreads();
    }
}

__global__ void k_fillcsr(const int* __restrict__ ei) {
    int e = blockIdx.x * blockDim.x + threadIdx.x;
    if (e < NE) {
        int dst = ei[NE + e];
        int pos = g_rowptr[dst] + atomicAdd(&g_fill[dst], 1);
        g_colsrc[pos] = ei[e];
    }
}

// ---------------- aggregation: warp/node, fused BN+ReLU on source, split bf16 output ----------------
template <int APPLY>
__global__ void k_agg(const float* __restrict__ src) {
    int w = (blockIdx.x * blockDim.x + threadIdx.x) >> 5;
    int lane = threadIdx.x & 31;
    if (w >= NN) return;
    float4 sc, sf;
    if (APPLY) {
        sc = *(const float4*)&g_scale[lane * 4];
        sf = *(const float4*)&g_shift[lane * 4];
    }
    const float4* hv = (const float4*)src;
    float4 self = hv[w * 32 + lane];
    float4 acc;
    if (APPLY) {
        acc.x = fmaxf(self.x * sc.x + sf.x, 0.f);
        acc.y = fmaxf(self.y * sc.y + sf.y, 0.f);
        acc.z = fmaxf(self.z * sc.z + sf.z, 0.f);
        acc.w = fmaxf(self.w * sc.w + sf.w, 0.f);
    } else acc = self;
    int e = g_rowptr[w], eend = g_rowptr[w + 1];
    for (; e + 4 <= eend; e += 4) {
        int s0 = g_colsrc[e + 0], s1 = g_colsrc[e + 1];
        int s2 = g_colsrc[e + 2], s3 = g_colsrc[e + 3];
        float4 v0 = hv[s0 * 32 + lane];
        float4 v1 = hv[s1 * 32 + lane];
        float4 v2 = hv[s2 * 32 + lane];
        float4 v3 = hv[s3 * 32 + lane];
        if (APPLY) {
            v0.x = fmaxf(v0.x * sc.x + sf.x, 0.f); v0.y = fmaxf(v0.y * sc.y + sf.y, 0.f);
            v0.z = fmaxf(v0.z * sc.z + sf.z, 0.f); v0.w = fmaxf(v0.w * sc.w + sf.w, 0.f);
            v1.x = fmaxf(v1.x * sc.x + sf.x, 0.f); v1.y = fmaxf(v1.y * sc.y + sf.y, 0.f);
            v1.z = fmaxf(v1.z * sc.z + sf.z, 0.f); v1.w = fmaxf(v1.w * sc.w + sf.w, 0.f);
            v2.x = fmaxf(v2.x * sc.x + sf.x, 0.f); v2.y = fmaxf(v2.y * sc.y + sf.y, 0.f);
            v2.z = fmaxf(v2.z * sc.z + sf.z, 0.f); v2.w = fmaxf(v2.w * sc.w + sf.w, 0.f);
            v3.x = fmaxf(v3.x * sc.x + sf.x, 0.f); v3.y = fmaxf(v3.y * sc.y + sf.y, 0.f);
            v3.z = fmaxf(v3.z * sc.z + sf.z, 0.f); v3.w = fmaxf(v3.w * sc.w + sf.w, 0.f);
        }
        acc.x += (v0.x + v1.x) + (v2.x + v3.x);
        acc.y += (v0.y + v1.y) + (v2.y + v3.y);
        acc.z += (v0.z + v1.z) + (v2.z + v3.z);
        acc.w += (v0.w + v1.w) + (v2.w + v3.w);
    }
    for (; e < eend; e++) {
        int s = g_colsrc[e];
        float4 v = hv[s * 32 + lane];
        if (APPLY) {
            v.x = fmaxf(v.x * sc.x + sf.x, 0.f); v.y = fmaxf(v.y * sc.y + sf.y, 0.f);
            v.z = fmaxf(v.z * sc.z + sf.z, 0.f); v.w = fmaxf(v.w * sc.w + sf.w, 0.f);
        }
        acc.x += v.x; acc.y += v.y; acc.z += v.z; acc.w += v.w;
    }
    // split -> hi/lo planes
    float a4[4] = {acc.x, acc.y, acc.z, acc.w};
    B4 hi, lo;
#pragma unroll
    for (int e2 = 0; e2 < 4; e2++) {
        __nv_bfloat16 h = __float2bfloat16_rn(a4[e2]);
        hi.b[e2] = h;
        lo.b[e2] = __float2bfloat16_rn(a4[e2] - __bfloat162float(h));
    }
    *(unsigned long long*)&g_ahi[w * 128 + lane * 4] = hi.u;
    *(unsigned long long*)&g_alo[w * 128 + lane * 4] = lo.u;
}

// ---------------- fused double GEMM, double-buffered cp.async ----------------
typedef wmma::fragment<wmma::matrix_a, 16, 16, 16, __nv_bfloat16, wmma::row_major> FragA;
typedef wmma::fragment<wmma::matrix_b, 16, 16, 16, __nv_bfloat16, wmma::row_major> FragB;
typedef wmma::fragment<wmma::accumulator, 16, 16, 16, float> FragC;

// warp tile: 16 rows x 32 cols. wy in {0,1}, wx in {0..3}.
__device__ __forceinline__ void gemm_pass32(const __nv_bfloat16* Ahi, const __nv_bfloat16* Alo,
                                            const __nv_bfloat16* Whi, const __nv_bfloat16* Wlo,
                                            FragC c[2], int wy, int wx) {
    wmma::fill_fragment(c[0], 0.f);
    wmma::fill_fragment(c[1], 0.f);
#pragma unroll
    for (int kk = 0; kk < 8; kk++) {
        FragA ahi, alo;
        wmma::load_matrix_sync(ahi, Ahi + (wy * 16) * LDA + kk * 16, LDA);
        wmma::load_matrix_sync(alo, Alo + (wy * 16) * LDA + kk * 16, LDA);
#pragma unroll
        for (int j = 0; j < 2; j++) {
            FragB bhi, blo;
            wmma::load_matrix_sync(bhi, Whi + kk * 16 * LDA + wx * 32 + j * 16, LDA);
            wmma::load_matrix_sync(blo, Wlo + kk * 16 * LDA + wx * 32 + j * 16, LDA);
            wmma::mma_sync(c[j], ahi, bhi, c[j]);
            wmma::mma_sync(c[j], ahi, blo, c[j]);
            wmma::mma_sync(c[j], alo, bhi, c[j]);
        }
    }
}

__device__ __forceinline__ void prefetchA(uint32_t buf_base, int t, int tid) {
    // 1024 cp.async of 16B: 2 planes x 32 rows x 16 chunks
#pragma unroll
    for (int i = 0; i < 4; i++) {
        int idx = tid + i * 256;
        int p = idx >> 9;
        int rem = idx & 511;
        int r = rem >> 4, k = rem & 15;
        const __nv_bfloat16* srcp = (p ? g_alo : g_ahi) + (size_t)(t * TR + r) * 128 + k * 8;
        uint32_t dst = buf_base + p * 8704 + r * 272 + k * 16;
        cp16(dst, srcp);
    }
    cp_commit();
}

__global__ void __launch_bounds__(256, 1)
k_fgemm(const __nv_bfloat16* __restrict__ wimg, const float* __restrict__ b1,
        float* __restrict__ Z2) {
    extern __shared__ char sh[];
    uint32_t sbase = smem_u32(sh);
    __nv_bfloat16* Wt = (__nv_bfloat16*)(sh + SM_W);
    float* stg = (float*)(sh + SM_STG);
    int tid = threadIdx.x;
    int bid = blockIdx.x;
    int w = tid >> 5, wy = w >> 2, wx = w & 3;

    {   // weights: 139264 B = 8704 uint4
        const uint4* wg = (const uint4*)wimg;
        uint4* wd = (uint4*)Wt;
#pragma unroll
        for (int i = 0; i < 34; i++) {
            int idx = tid + i * 256;
            if (idx < 8704) wd[idx] = wg[idx];
        }
    }

    // prologue prefetch
    prefetchA(sbase + SM_ABUF, bid, tid);

    int buf = 0;
    for (int t = bid; t < NT; t += NBLK, buf ^= 1) {
        cp_wait0();
        __syncthreads();
        // prefetch next tile into other buffer
        int tn = t + NBLK;
        if (tn < NT) prefetchA(sbase + SM_ABUF + (buf ^ 1) * 17408, tn, tid);

        __nv_bfloat16* Ahi = (__nv_bfloat16*)(sh + SM_ABUF + buf * 17408);
        __nv_bfloat16* Alo = Ahi + 4352;       // 8704 bytes

        FragC c[2];
        // GEMM1: z1raw = A @ W1
        gemm_pass32(Ahi, Alo, Wt, Wt + 128 * LDA, c, wy, wx);
        wmma::store_matrix_sync(stg + (wy * 16) * LDSG + wx * 32, c[0], LDSG, wmma::mem_row_major);
        wmma::store_matrix_sync(stg + (wy * 16) * LDSG + wx * 32 + 16, c[1], LDSG, wmma::mem_row_major);
        __syncthreads();

        // z1 = relu(z1raw + b1) -> split -> overwrite current A buffer
#pragma unroll
        for (int ii = 0; ii < 2; ii++) {
            int i = tid + ii * 256;            // 0..511: 32 rows x 16 col-groups
            int r = i >> 4, c0 = (i & 15) << 3;
            B8 hi, lo;
#pragma unroll
            for (int e = 0; e < 8; e++) {
                float v = fmaxf(stg[r * LDSG + c0 + e] + b1[c0 + e], 0.f);
                __nv_bfloat16 h = __float2bfloat16_rn(v);
                hi.b[e] = h;
                lo.b[e] = __float2bfloat16_rn(v - __bfloat162float(h));
            }
            *(uint4*)&Ahi[r * LDA + c0] = hi.u;
            *(uint4*)&Alo[r * LDA + c0] = lo.u;
        }
        __syncthreads();

        // GEMM2: z2raw = z1 @ W2 -> direct global store (no bias: BN cancels it)
        gemm_pass32(Ahi, Alo, Wt + 2 * 128 * LDA, Wt + 3 * 128 * LDA, c, wy, wx);
        float* zout = Z2 + (size_t)(t * TR + wy * 16) * 128 + wx * 32;
        wmma::store_matrix_sync(zout, c[0], 128, wmma::mem_row_major);
        wmma::store_matrix_sync(zout + 16, c[1], 128, wmma::mem_row_major);
    }
}

// ---------------- column stats over z2raw ----------------
#define STAT_BLKS 250
#define STAT_CHUNK (NN / STAT_BLKS)   // 400
__global__ void k_stats() {
    int col = threadIdx.x & 127, half = threadIdx.x >> 7;
    int r0 = blockIdx.x * STAT_CHUNK;
    float s = 0.f, q = 0.f;
    for (int r = r0 + half; r < r0 + STAT_CHUNK; r += 2) {
        float v = g_z2[(size_t)r * 128 + col];
        s += v; q += v * v;
    }
    atomicAdd(&g_stats[col], s);
    atomicAdd(&g_stats[128 + col], q);
}

__global__ void k_finalize(const float* __restrict__ gamma, const float* __restrict__ beta) {
    int j = threadIdx.x;
    float mu = g_stats[j] * (1.0f / NN);
    float var = g_stats[128 + j] * (1.0f / NN) - mu * mu;
    float a = gamma[j] * rsqrtf(var + 1e-5f);
    g_scale[j] = a;
    g_shift[j] = beta[j] - mu * a;
    g_stats[j] = 0.f;
    g_stats[128 + j] = 0.f;
}

// ---------------- pooling (applies final BN) ----------------
__global__ void k_start(const int* __restrict__ batch) {
    int n = blockIdx.x * blockDim.x + threadIdx.x;
    if (n >= NN) return;
    int b = batch[n];
    if (n == 0) { for (int i = 0; i <= b; i++) g_start[i] = 0; }
    else {
        int p = batch[n - 1];
        for (int i = p + 1; i <= b; i++) g_start[i] = n;
    }
    if (n == NN - 1) { for (int i = b + 1; i <= NB; i++) g_start[i] = NN; }
}

__global__ void k_pool() {
    int b = blockIdx.x, j = threadIdx.x;
    int s = g_start[b], e = g_start[b + 1];
    float sc = g_scale[j], sf = g_shift[j];
    float sum = 0.f, mx = -3.402823466e38f;
    int n = s;
    for (; n + 2 <= e; n += 2) {
        float v0 = g_z2[(size_t)n * HD + j] * sc + sf;
        float v1 = g_z2[(size_t)(n + 1) * HD + j] * sc + sf;
        sum += v0 + v1;
        mx = fmaxf(mx, fmaxf(v0, v1));
    }
    for (; n < e; n++) {
        float v = g_z2[(size_t)n * HD + j] * sc + sf;
        sum += v; mx = fmaxf(mx, v);
    }
    int cnt = e - s;
    g_graph[b * 384 + j]       = cnt ? sum / (float)cnt : 0.f;
    g_graph[b * 384 + 128 + j] = cnt ? mx : 0.f;
    g_graph[b * 384 + 256 + j] = sum;
}

// ---------------- head ----------------
__global__ void k_head(const float* __restrict__ orders,
                       const float* __restrict__ oW1, const float* __restrict__ ob1,
                       const float* __restrict__ oW2, const float* __restrict__ ob2,
                       const float* __restrict__ sW1, const float* __restrict__ sb1,
                       const float* __restrict__ sW2, const float* __restrict__ sb2,
                       const float* __restrict__ sW3, const float* __restrict__ sb3,
                       float* __restrict__ out) {
    extern __shared__ float fsh[];
    float* comb  = fsh;                      // 32*512
    float* t_all = comb + 32 * 512;          // 32*128
    float* s2m   = t_all + 32 * 128;         // 32*68
    float* ords  = s2m + 32 * 68;            // 32*33
    int b = blockIdx.x, tid = threadIdx.x;

    for (int idx = tid; idx < 32 * 384; idx += 128) {
        int o = idx / 384, k = idx - o * 384;
        comb[o * 512 + k] = g_graph[b * 384 + k];
    }
    for (int idx = tid; idx < 32 * 32; idx += 128) {
        int o = idx >> 5, k = idx & 31;
        ords[o * 33 + k] = orders[(b * 32 + o) * 32 + k];
    }
    __syncthreads();

    int tcol = tid & 31, tord = tid >> 5;

    {   // t = relu(ords @ oW1 + ob1)
        float4 bc = *(const float4*)&ob1[tcol * 4];
        float acc[8][4];
#pragma unroll
        for (int i = 0; i < 8; i++) { acc[i][0] = bc.x; acc[i][1] = bc.y; acc[i][2] = bc.z; acc[i][3] = bc.w; }
#pragma unroll
        for (int k = 0; k < 32; k++) {
            float4 wv = *(const float4*)&oW1[k * 128 + tcol * 4];
#pragma unroll
            for (int i = 0; i < 8; i++) {
                float a = ords[(tord * 8 + i) * 33 + k];
                acc[i][0] += a * wv.x; acc[i][1] += a * wv.y;
                acc[i][2] += a * wv.z; acc[i][3] += a * wv.w;
            }
        }
#pragma unroll
        for (int i = 0; i < 8; i++)
            *(float4*)&t_all[(tord * 8 + i) * 128 + tcol * 4] =
                make_float4(fmaxf(acc[i][0], 0.f), fmaxf(acc[i][1], 0.f),
                            fmaxf(acc[i][2], 0.f), fmaxf(acc[i][3], 0.f));
    }
    __syncthreads();

    {   // oe = t @ oW2 + ob2 -> comb[:,384:]
        float4 bc = *(const float4*)&ob2[tcol * 4];
        float acc[8][4];
#pragma unroll
        for (int i = 0; i < 8; i++) { acc[i][0] = bc.x; acc[i][1] = bc.y; acc[i][2] = bc.z; acc[i][3] = bc.w; }
#pragma unroll 4
        for (int k = 0; k < 128; k++) {
            float4 wv = *(const float4*)&oW2[k * 128 + tcol * 4];
#pragma unroll
            for (int i = 0; i < 8; i++) {
                float a = t_all[(tord * 8 + i) * 128 + k];
                acc[i][0] += a * wv.x; acc[i][1] += a * wv.y;
                acc[i][2] += a * wv.z; acc[i][3] += a * wv.w;
            }
        }
        __syncthreads();
#pragma unroll
        for (int i = 0; i < 8; i++)
            *(float4*)&comb[(tord * 8 + i) * 512 + 384 + tcol * 4] =
                make_float4(acc[i][0], acc[i][1], acc[i][2], acc[i][3]);
    }
    __syncthreads();

    {   // s1 = relu(comb @ sW1 + sb1)
        float4 bc = *(const float4*)&sb1[tcol * 4];
        float acc[8][4];
#pragma unroll
        for (int i = 0; i < 8; i++) { acc[i][0] = bc.x; acc[i][1] = bc.y; acc[i][2] = bc.z; acc[i][3] = bc.w; }
#pragma unroll 4
        for (int k = 0; k < 512; k++) {
            float4 wv = *(const float4*)&sW1[k * 128 + tcol * 4];
#pragma unroll
            for (int i = 0; i < 8; i++) {
                float a = comb[(tord * 8 + i) * 512 + k];
                acc[i][0] += a * wv.x; acc[i][1] += a * wv.y;
                acc[i][2] += a * wv.z; acc[i][3] += a * wv.w;
            }
        }
#pragma unroll
        for (int i = 0; i < 8; i++)
            *(float4*)&t_all[(tord * 8 + i) * 128 + tcol * 4] =
                make_float4(fmaxf(acc[i][0], 0.f), fmaxf(acc[i][1], 0.f),
                            fmaxf(acc[i][2], 0.f), fmaxf(acc[i][3], 0.f));
    }
    __syncthreads();

    {   // s2 = relu(s1 @ sW2 + sb2)
        int tc2 = tid & 15, to2 = tid >> 4;
        float4 bc = *(const float4*)&sb2[tc2 * 4];
        float acc[4][4];
#pragma unroll
        for (int i = 0; i < 4; i++) { acc[i][0] = bc.x; acc[i][1] = bc.y; acc[i][2] = bc.z; acc[i][3] = bc.w; }
#pragma unroll 4
        for (int k = 0; k < 128; k++) {
            float4 wv = *(const float4*)&sW2[k * 64 + tc2 * 4];
#pragma unroll
            for (int i = 0; i < 4; i++) {
                float a = t_all[(to2 * 4 + i) * 128 + k];
                acc[i][0] += a * wv.x; acc[i][1] += a * wv.y;
                acc[i][2] += a * wv.z; acc[i][3] += a * wv.w;
            }
        }
#pragma unroll
        for (int i = 0; i < 4; i++)
            *(float4*)&s2m[(to2 * 4 + i) * 68 + tc2 * 4] =
                make_float4(fmaxf(acc[i][0], 0.f), fmaxf(acc[i][1], 0.f),
                            fmaxf(acc[i][2], 0.f), fmaxf(acc[i][3], 0.f));
    }
    __syncthreads();

    if (tid < 32) {
        float acc = sb3[0];
#pragma unroll 8
        for (int k = 0; k < 64; k++) acc += s2m[tid * 68 + k] * sW3[k];
        out[b * 32 + tid] = acc;
    }
}

// ---------------- launch ----------------
extern "C" void kernel_launch(void* const* d_in, const int* in_sizes, int n_in,
                              void* d_out, int out_size) {
    const float* x      = (const float*)d_in[0];
    const int*   ei     = (const int*)d_in[1];
    const float* orders = (const float*)d_in[2];
    const int*   batch  = (const int*)d_in[3];
    const float* gW1    = (const float*)d_in[4];
    const float* gb1    = (const float*)d_in[5];
    const float* gW2    = (const float*)d_in[6];
    // gb2 (d_in[7]) intentionally unused: BN cancels the second bias
    const float* gamma  = (const float*)d_in[8];
    const float* beta   = (const float*)d_in[9];
    const float* oW1    = (const float*)d_in[10];
    const float* ob1    = (const float*)d_in[11];
    const float* oW2    = (const float*)d_in[12];
    const float* ob2    = (const float*)d_in[13];
    const float* sW1    = (const float*)d_in[14];
    const float* sb1    = (const float*)d_in[15];
    const float* sW2    = (const float*)d_in[16];
    const float* sb2    = (const float*)d_in[17];
    const float* sW3    = (const float*)d_in[18];
    const float* sb3    = (const float*)d_in[19];
    float* out = (float*)d_out;

    void *p_z2, *p_wimg;
    cudaGetSymbolAddress(&p_z2,   g_z2);
    cudaGetSymbolAddress(&p_wimg, g_wimg);

    size_t head_smem = (size_t)(32 * 512 + 32 * 128 + 32 * 68 + 32 * 33) * 4;
    cudaFuncSetAttribute(k_head, cudaFuncAttributeMaxDynamicSharedMemorySize, (int)head_smem);
    cudaFuncSetAttribute(k_fgemm, cudaFuncAttributeMaxDynamicSharedMemorySize, FG_SMEM);

    k_zero<<<(NN + 1 + 255) / 256, 256>>>();
    k_hist<<<(NE + 255) / 256, 256>>>(ei);
    k_scan<<<1, 1024>>>();
    k_fillcsr<<<(NE + 255) / 256, 256>>>(ei);
    k_prepw<<<(NL * 2 * 16384 + 255) / 256, 256>>>(gW1, gW2);

    for (int l = 0; l < NL; l++) {
        if (l == 0) k_agg<0><<<(NN * 32 + 255) / 256, 256>>>(x);
        else        k_agg<1><<<(NN * 32 + 255) / 256, 256>>>((const float*)p_z2);
        k_fgemm<<<NBLK, 256, FG_SMEM>>>((const __nv_bfloat16*)p_wimg + (size_t)l * 4 * 128 * LDA,
                                        gb1 + l * HD, (float*)p_z2);
        k_stats<<<STAT_BLKS, 256>>>();
        k_finalize<<<1, 128>>>(gamma + l * HD, beta + l * HD);
    }

    k_start<<<(NN + 255) / 256, 256>>>(batch);
    k_pool<<<NB, 128>>>();
    k_head<<<NB, 128, head_smem>>>(orders, oW1, ob1, oW2, ob2,
                                   sW1, sb1, sW2, sb2, sW3, sb3, out);
}

// round 6
// speedup vs baseline: 1.0014x; 1.0014x over previous
#include <cuda_runtime.h>
#include <cuda_bf16.h>
#include <mma.h>
#include <math.h>
#include <stdint.h>

using namespace nvcuda;

#define NN 100000
#define NE 1600000
#define NB 256
#define HD 128
#define NL 3

#define TR 32
#define NT (NN / TR)          // 3125 exact
#define NBLK 148
#define LDA 136               // bf16 smem stride
#define LDSG 132              // f32 staging stride
#define WTILE_B (128 * LDA * 2)   // 34816 bytes per 128x136 bf16 weight tile

// smem map for fgemm
#define SM_ABUF 0                         // 2 buffers x (hi 8704 + lo 8704) = 34816
#define SM_W    34816                     // 4 tiles = 139264
#define SM_STG  (34816 + 139264)          // 32*132*4 = 16896
#define FG_SMEM (SM_STG + TR * LDSG * 4)  // 190976

// ---------------- device scratch ----------------
__device__ __align__(16) __nv_bfloat16 g_ahi[NN * HD];
__device__ __align__(16) __nv_bfloat16 g_alo[NN * HD];
__device__ float g_z2[NN * HD];
__device__ int   g_rowptr[NN + 1];
__device__ int   g_fill[NN];
__device__ int   g_colsrc[NE];
__device__ float g_stats[2 * HD];
__device__ float g_scale[HD];
__device__ float g_shift[HD];
__device__ float g_graph[NB * 3 * HD];
__device__ int   g_start[NB + 1];
__device__ __align__(16) __nv_bfloat16 g_wimg[NL * 4 * 128 * LDA];

union B8 { uint4 u; __nv_bfloat16 b[8]; };
union B4 { unsigned long long u; __nv_bfloat16 b[4]; };

__device__ __forceinline__ uint32_t smem_u32(const void* p) {
    uint32_t a;
    asm("{ .reg .u64 t; cvta.to.shared.u64 t, %1; cvt.u32.u64 %0, t; }" : "=r"(a) : "l"(p));
    return a;
}
__device__ __forceinline__ void cp16(uint32_t dst, const void* src) {
    asm volatile("cp.async.cg.shared.global [%0], [%1], 16;" :: "r"(dst), "l"(src));
}
__device__ __forceinline__ void cp_commit() { asm volatile("cp.async.commit_group;"); }
__device__ __forceinline__ void cp_wait0()  { asm volatile("cp.async.wait_group 0;"); }

// ---------------- init / weight prep ----------------
__global__ void k_zero() {
    int i = blockIdx.x * blockDim.x + threadIdx.x;
    if (i <= NN) g_rowptr[i] = 0;
    if (i < NN)  g_fill[i] = 0;
    if (i < 2 * HD) g_stats[i] = 0.f;
}

__global__ void k_prepw(const float* __restrict__ gW1, const float* __restrict__ gW2) {
    int idx = blockIdx.x * blockDim.x + threadIdx.x;
    if (idx >= NL * 2 * 16384) return;
    int l = idx / 32768;
    int rem = idx - l * 32768;
    int m = rem >> 14;
    int e = rem & 16383;
    int k = e >> 7;
    int n = e & 127;
    float v = (m ? gW2 : gW1)[l * 16384 + k * 128 + n];
    __nv_bfloat16 hi = __float2bfloat16_rn(v);
    __nv_bfloat16 lo = __float2bfloat16_rn(v - __bfloat162float(hi));
    __nv_bfloat16* base = g_wimg + (size_t)(l * 4 + m * 2) * 128 * LDA;
    base[k * LDA + n] = hi;
    base[128 * LDA + k * LDA + n] = lo;
}

// ---------------- CSR build ----------------
__global__ void k_hist(const int* __restrict__ ei) {
    int e = blockIdx.x * blockDim.x + threadIdx.x;
    if (e < NE) atomicAdd(&g_rowptr[ei[NE + e] + 1], 1);
}

__global__ void k_scan() {
    __shared__ int wsum[32];
    __shared__ int carry;
    int tid = threadIdx.x, lane = tid & 31, wid = tid >> 5;
    if (tid == 0) carry = 0;
    const int NCH = (NN + 1 + 1023) / 1024;
    int nv = g_rowptr[tid];
    __syncthreads();
    for (int ch = 0; ch < NCH; ch++) {
        int v = nv;
        if (ch + 1 < NCH) {
            int gn = (ch + 1) * 1024 + tid;
            nv = (gn <= NN) ? g_rowptr[gn] : 0;
        }
        int x = v;
#pragma unroll
        for (int d = 1; d < 32; d <<= 1) { int y = __shfl_up_sync(0xFFFFFFFFu, x, d); if (lane >= d) x += y; }
        if (lane == 31) wsum[wid] = x;
        __syncthreads();
        if (wid == 0) {
            int y = wsum[lane];
#pragma unroll
            for (int d = 1; d < 32; d <<= 1) { int z = __shfl_up_sync(0xFFFFFFFFu, y, d); if (lane >= d) y += z; }
            wsum[lane] = y;
        }
        __syncthreads();
        if (wid > 0) x += wsum[wid - 1];
        int out = x + carry;
        int gid = ch * 1024 + tid;
        if (gid <= NN) g_rowptr[gid] = out;
        __syncthreads();
        if (tid == 1023) carry = out;
        __syncthreads();
    }
}

__global__ void k_fillcsr(const int* __restrict__ ei) {
    int e = blockIdx.x * blockDim.x + threadIdx.x;
    if (e < NE) {
        int dst = ei[NE + e];
        int pos = g_rowptr[dst] + atomicAdd(&g_fill[dst], 1);
        g_colsrc[pos] = ei[e];
    }
}

// ---------------- aggregation: warp/node, fused BN+ReLU on source, split bf16 output ----------------
template <int APPLY>
__global__ void k_agg(const float* __restrict__ src) {
    int w = (blockIdx.x * blockDim.x + threadIdx.x) >> 5;
    int lane = threadIdx.x & 31;
    if (w >= NN) return;
    float4 sc, sf;
    if (APPLY) {
        sc = *(const float4*)&g_scale[lane * 4];
        sf = *(const float4*)&g_shift[lane * 4];
    }
    const float4* hv = (const float4*)src;
    float4 self = hv[w * 32 + lane];
    float4 acc;
    if (APPLY) {
        acc.x = fmaxf(self.x * sc.x + sf.x, 0.f);
        acc.y = fmaxf(self.y * sc.y + sf.y, 0.f);
        acc.z = fmaxf(self.z * sc.z + sf.z, 0.f);
        acc.w = fmaxf(self.w * sc.w + sf.w, 0.f);
    } else acc = self;
    int e = g_rowptr[w], eend = g_rowptr[w + 1];
    for (; e + 4 <= eend; e += 4) {
        int s0 = g_colsrc[e + 0], s1 = g_colsrc[e + 1];
        int s2 = g_colsrc[e + 2], s3 = g_colsrc[e + 3];
        float4 v0 = hv[s0 * 32 + lane];
        float4 v1 = hv[s1 * 32 + lane];
        float4 v2 = hv[s2 * 32 + lane];
        float4 v3 = hv[s3 * 32 + lane];
        if (APPLY) {
            v0.x = fmaxf(v0.x * sc.x + sf.x, 0.f); v0.y = fmaxf(v0.y * sc.y + sf.y, 0.f);
            v0.z = fmaxf(v0.z * sc.z + sf.z, 0.f); v0.w = fmaxf(v0.w * sc.w + sf.w, 0.f);
            v1.x = fmaxf(v1.x * sc.x + sf.x, 0.f); v1.y = fmaxf(v1.y * sc.y + sf.y, 0.f);
            v1.z = fmaxf(v1.z * sc.z + sf.z, 0.f); v1.w = fmaxf(v1.w * sc.w + sf.w, 0.f);
            v2.x = fmaxf(v2.x * sc.x + sf.x, 0.f); v2.y = fmaxf(v2.y * sc.y + sf.y, 0.f);
            v2.z = fmaxf(v2.z * sc.z + sf.z, 0.f); v2.w = fmaxf(v2.w * sc.w + sf.w, 0.f);
            v3.x = fmaxf(v3.x * sc.x + sf.x, 0.f); v3.y = fmaxf(v3.y * sc.y + sf.y, 0.f);
            v3.z = fmaxf(v3.z * sc.z + sf.z, 0.f); v3.w = fmaxf(v3.w * sc.w + sf.w, 0.f);
        }
        acc.x += (v0.x + v1.x) + (v2.x + v3.x);
        acc.y += (v0.y + v1.y) + (v2.y + v3.y);
        acc.z += (v0.z + v1.z) + (v2.z + v3.z);
        acc.w += (v0.w + v1.w) + (v2.w + v3.w);
    }
    for (; e < eend; e++) {
        int s = g_colsrc[e];
        float4 v = hv[s * 32 + lane];
        if (APPLY) {
            v.x = fmaxf(v.x * sc.x + sf.x, 0.f); v.y = fmaxf(v.y * sc.y + sf.y, 0.f);
            v.z = fmaxf(v.z * sc.z + sf.z, 0.f); v.w = fmaxf(v.w * sc.w + sf.w, 0.f);
        }
        acc.x += v.x; acc.y += v.y; acc.z += v.z; acc.w += v.w;
    }
    // split -> hi/lo planes
    float a4[4] = {acc.x, acc.y, acc.z, acc.w};
    B4 hi, lo;
#pragma unroll
    for (int e2 = 0; e2 < 4; e2++) {
        __nv_bfloat16 h = __float2bfloat16_rn(a4[e2]);
        hi.b[e2] = h;
        lo.b[e2] = __float2bfloat16_rn(a4[e2] - __bfloat162float(h));
    }
    *(unsigned long long*)&g_ahi[w * 128 + lane * 4] = hi.u;
    *(unsigned long long*)&g_alo[w * 128 + lane * 4] = lo.u;
}

// ---------------- fused double GEMM, double-buffered cp.async ----------------
typedef wmma::fragment<wmma::matrix_a, 16, 16, 16, __nv_bfloat16, wmma::row_major> FragA;
typedef wmma::fragment<wmma::matrix_b, 16, 16, 16, __nv_bfloat16, wmma::row_major> FragB;
typedef wmma::fragment<wmma::accumulator, 16, 16, 16, float> FragC;

// warp tile: 16 rows x 32 cols. wy in {0,1}, wx in {0..3}.
__device__ __forceinline__ void gemm_pass32(const __nv_bfloat16* Ahi, const __nv_bfloat16* Alo,
                                            const __nv_bfloat16* Whi, const __nv_bfloat16* Wlo,
                                            FragC c[2], int wy, int wx) {
    wmma::fill_fragment(c[0], 0.f);
    wmma::fill_fragment(c[1], 0.f);
#pragma unroll
    for (int kk = 0; kk < 8; kk++) {
        FragA ahi, alo;
        wmma::load_matrix_sync(ahi, Ahi + (wy * 16) * LDA + kk * 16, LDA);
        wmma::load_matrix_sync(alo, Alo + (wy * 16) * LDA + kk * 16, LDA);
#pragma unroll
        for (int j = 0; j < 2; j++) {
            FragB bhi, blo;
            wmma::load_matrix_sync(bhi, Whi + kk * 16 * LDA + wx * 32 + j * 16, LDA);
            wmma::load_matrix_sync(blo, Wlo + kk * 16 * LDA + wx * 32 + j * 16, LDA);
            wmma::mma_sync(c[j], ahi, bhi, c[j]);
            wmma::mma_sync(c[j], ahi, blo, c[j]);
            wmma::mma_sync(c[j], alo, bhi, c[j]);
        }
    }
}

__device__ __forceinline__ void prefetchA(uint32_t buf_base, int t, int tid) {
    // 1024 cp.async of 16B: 2 planes x 32 rows x 16 chunks
#pragma unroll
    for (int i = 0; i < 4; i++) {
        int idx = tid + i * 256;
        int p = idx >> 9;
        int rem = idx & 511;
        int r = rem >> 4, k = rem & 15;
        const __nv_bfloat16* srcp = (p ? g_alo : g_ahi) + (size_t)(t * TR + r) * 128 + k * 8;
        uint32_t dst = buf_base + p * 8704 + r * 272 + k * 16;
        cp16(dst, srcp);
    }
    cp_commit();
}

__global__ void __launch_bounds__(256, 1)
k_fgemm(const __nv_bfloat16* __restrict__ wimg, const float* __restrict__ b1,
        float* __restrict__ Z2) {
    extern __shared__ char sh[];
    uint32_t sbase = smem_u32(sh);
    __nv_bfloat16* Wt = (__nv_bfloat16*)(sh + SM_W);
    float* stg = (float*)(sh + SM_STG);
    int tid = threadIdx.x;
    int bid = blockIdx.x;
    int w = tid >> 5, wy = w >> 2, wx = w & 3;

    {   // weights: 139264 B = 8704 uint4
        const uint4* wg = (const uint4*)wimg;
        uint4* wd = (uint4*)Wt;
#pragma unroll
        for (int i = 0; i < 34; i++) {
            int idx = tid + i * 256;
            if (idx < 8704) wd[idx] = wg[idx];
        }
    }

    // prologue prefetch
    prefetchA(sbase + SM_ABUF, bid, tid);

    int buf = 0;
    for (int t = bid; t < NT; t += NBLK, buf ^= 1) {
        cp_wait0();
        __syncthreads();
        // prefetch next tile into other buffer
        int tn = t + NBLK;
        if (tn < NT) prefetchA(sbase + SM_ABUF + (buf ^ 1) * 17408, tn, tid);

        __nv_bfloat16* Ahi = (__nv_bfloat16*)(sh + SM_ABUF + buf * 17408);
        __nv_bfloat16* Alo = Ahi + 4352;       // 8704 bytes

        FragC c[2];
        // GEMM1: z1raw = A @ W1
        gemm_pass32(Ahi, Alo, Wt, Wt + 128 * LDA, c, wy, wx);
        wmma::store_matrix_sync(stg + (wy * 16) * LDSG + wx * 32, c[0], LDSG, wmma::mem_row_major);
        wmma::store_matrix_sync(stg + (wy * 16) * LDSG + wx * 32 + 16, c[1], LDSG, wmma::mem_row_major);
        __syncthreads();

        // z1 = relu(z1raw + b1) -> split -> overwrite current A buffer
#pragma unroll
        for (int ii = 0; ii < 2; ii++) {
            int i = tid + ii * 256;            // 0..511: 32 rows x 16 col-groups
            int r = i >> 4, c0 = (i & 15) << 3;
            B8 hi, lo;
#pragma unroll
            for (int e = 0; e < 8; e++) {
                float v = fmaxf(stg[r * LDSG + c0 + e] + b1[c0 + e], 0.f);
                __nv_bfloat16 h = __float2bfloat16_rn(v);
                hi.b[e] = h;
                lo.b[e] = __float2bfloat16_rn(v - __bfloat162float(h));
            }
            *(uint4*)&Ahi[r * LDA + c0] = hi.u;
            *(uint4*)&Alo[r * LDA + c0] = lo.u;
        }
        __syncthreads();

        // GEMM2: z2raw = z1 @ W2 -> direct global store (no bias: BN cancels it)
        gemm_pass32(Ahi, Alo, Wt + 2 * 128 * LDA, Wt + 3 * 128 * LDA, c, wy, wx);
        float* zout = Z2 + (size_t)(t * TR + wy * 16) * 128 + wx * 32;
        wmma::store_matrix_sync(zout, c[0], 128, wmma::mem_row_major);
        wmma::store_matrix_sync(zout + 16, c[1], 128, wmma::mem_row_major);
    }
}

// ---------------- column stats over z2raw ----------------
#define STAT_BLKS 250
#define STAT_CHUNK (NN / STAT_BLKS)   // 400
__global__ void k_stats() {
    int col = threadIdx.x & 127, half = threadIdx.x >> 7;
    int r0 = blockIdx.x * STAT_CHUNK;
    float s = 0.f, q = 0.f;
    for (int r = r0 + half; r < r0 + STAT_CHUNK; r += 2) {
        float v = g_z2[(size_t)r * 128 + col];
        s += v; q += v * v;
    }
    atomicAdd(&g_stats[col], s);
    atomicAdd(&g_stats[128 + col], q);
}

__global__ void k_finalize(const float* __restrict__ gamma, const float* __restrict__ beta) {
    int j = threadIdx.x;
    float mu = g_stats[j] * (1.0f / NN);
    float var = g_stats[128 + j] * (1.0f / NN) - mu * mu;
    float a = gamma[j] * rsqrtf(var + 1e-5f);
    g_scale[j] = a;
    g_shift[j] = beta[j] - mu * a;
    g_stats[j] = 0.f;
    g_stats[128 + j] = 0.f;
}

// ---------------- pooling (applies final BN) ----------------
__global__ void k_start(const int* __restrict__ batch) {
    int n = blockIdx.x * blockDim.x + threadIdx.x;
    if (n >= NN) return;
    int b = batch[n];
    if (n == 0) { for (int i = 0; i <= b; i++) g_start[i] = 0; }
    else {
        int p = batch[n - 1];
        for (int i = p + 1; i <= b; i++) g_start[i] = n;
    }
    if (n == NN - 1) { for (int i = b + 1; i <= NB; i++) g_start[i] = NN; }
}

__global__ void k_pool() {
    int b = blockIdx.x, j = threadIdx.x;
    int s = g_start[b], e = g_start[b + 1];
    float sc = g_scale[j], sf = g_shift[j];
    float sum = 0.f, mx = -3.402823466e38f;
    int n = s;
    for (; n + 2 <= e; n += 2) {
        float v0 = g_z2[(size_t)n * HD + j] * sc + sf;
        float v1 = g_z2[(size_t)(n + 1) * HD + j] * sc + sf;
        sum += v0 + v1;
        mx = fmaxf(mx, fmaxf(v0, v1));
    }
    for (; n < e; n++) {
        float v = g_z2[(size_t)n * HD + j] * sc + sf;
        sum += v; mx = fmaxf(mx, v);
    }
    int cnt = e - s;
    g_graph[b * 384 + j]       = cnt ? sum / (float)cnt : 0.f;
    g_graph[b * 384 + 128 + j] = cnt ? mx : 0.f;
    g_graph[b * 384 + 256 + j] = sum;
}

// ---------------- head ----------------
__global__ void k_head(const float* __restrict__ orders,
                       const float* __restrict__ oW1, const float* __restrict__ ob1,
                       const float* __restrict__ oW2, const float* __restrict__ ob2,
                       const float* __restrict__ sW1, const float* __restrict__ sb1,
                       const float* __restrict__ sW2, const float* __restrict__ sb2,
                       const float* __restrict__ sW3, const float* __restrict__ sb3,
                       float* __restrict__ out) {
    extern __shared__ float fsh[];
    float* comb  = fsh;                      // 32*512
    float* t_all = comb + 32 * 512;          // 32*128
    float* s2m   = t_all + 32 * 128;         // 32*68
    float* ords  = s2m + 32 * 68;            // 32*33
    int b = blockIdx.x, tid = threadIdx.x;

    for (int idx = tid; idx < 32 * 384; idx += 128) {
        int o = idx / 384, k = idx - o * 384;
        comb[o * 512 + k] = g_graph[b * 384 + k];
    }
    for (int idx = tid; idx < 32 * 32; idx += 128) {
        int o = idx >> 5, k = idx & 31;
        ords[o * 33 + k] = orders[(b * 32 + o) * 32 + k];
    }
    __syncthreads();

    int tcol = tid & 31, tord = tid >> 5;

    {   // t = relu(ords @ oW1 + ob1)
        float4 bc = *(const float4*)&ob1[tcol * 4];
        float acc[8][4];
#pragma unroll
        for (int i = 0; i < 8; i++) { acc[i][0] = bc.x; acc[i][1] = bc.y; acc[i][2] = bc.z; acc[i][3] = bc.w; }
#pragma unroll
        for (int k = 0; k < 32; k++) {
            float4 wv = *(const float4*)&oW1[k * 128 + tcol * 4];
#pragma unroll
            for (int i = 0; i < 8; i++) {
                float a = ords[(tord * 8 + i) * 33 + k];
                acc[i][0] += a * wv.x; acc[i][1] += a * wv.y;
                acc[i][2] += a * wv.z; acc[i][3] += a * wv.w;
            }
        }
#pragma unroll
        for (int i = 0; i < 8; i++)
            *(float4*)&t_all[(tord * 8 + i) * 128 + tcol * 4] =
                make_float4(fmaxf(acc[i][0], 0.f), fmaxf(acc[i][1], 0.f),
                            fmaxf(acc[i][2], 0.f), fmaxf(acc[i][3], 0.f));
    }
    __syncthreads();

    {   // oe = t @ oW2 + ob2 -> comb[:,384:]
        float4 bc = *(const float4*)&ob2[tcol * 4];
        float acc[8][4];
#pragma unroll
        for (int i = 0; i < 8; i++) { acc[i][0] = bc.x; acc[i][1] = bc.y; acc[i][2] = bc.z; acc[i][3] = bc.w; }
#pragma unroll 4
        for (int k = 0; k < 128; k++) {
            float4 wv = *(const float4*)&oW2[k * 128 + tcol * 4];
#pragma unroll
            for (int i = 0; i < 8; i++) {
                float a = t_all[(tord * 8 + i) * 128 + k];
                acc[i][0] += a * wv.x; acc[i][1] += a * wv.y;
                acc[i][2] += a * wv.z; acc[i][3] += a * wv.w;
            }
        }
        __syncthreads();
#pragma unroll
        for (int i = 0; i < 8; i++)
            *(float4*)&comb[(tord * 8 + i) * 512 + 384 + tcol * 4] =
                make_float4(acc[i][0], acc[i][1], acc[i][2], acc[i][3]);
    }
    __syncthreads();

    {   // s1 = relu(comb @ sW1 + sb1)
        float4 bc = *(const float4*)&sb1[tcol * 4];
        float acc[8][4];
#pragma unroll
        for (int i = 0; i < 8; i++) { acc[i][0] = bc.x; acc[i][1] = bc.y; acc[i][2] = bc.z; acc[i][3] = bc.w; }
#pragma unroll 4
        for (int k = 0; k < 512; k++) {
            float4 wv = *(const float4*)&sW1[k * 128 + tcol * 4];
#pragma unroll
            for (int i = 0; i < 8; i++) {
                float a = comb[(tord * 8 + i) * 512 + k];
                acc[i][0] += a * wv.x; acc[i][1] += a * wv.y;
                acc[i][2] += a * wv.z; acc[i][3] += a * wv.w;
            }
        }
#pragma unroll
        for (int i = 0; i < 8; i++)
            *(float4*)&t_all[(tord * 8 + i) * 128 + tcol * 4] =
                make_float4(fmaxf(acc[i][0], 0.f), fmaxf(acc[i][1], 0.f),
                            fmaxf(acc[i][2], 0.f), fmaxf(acc[i][3], 0.f));
    }
    __syncthreads();

    {   // s2 = relu(s1 @ sW2 + sb2)
        int tc2 = tid & 15, to2 = tid >> 4;
        float4 bc = *(const float4*)&sb2[tc2 * 4];
        float acc[4][4];
#pragma unroll
        for (int i = 0; i < 4; i++) { acc[i][0] = bc.x; acc[i][1] = bc.y; acc[i][2] = bc.z; acc[i][3] = bc.w; }
#pragma unroll 4
        for (int k = 0; k < 128; k++) {
            float4 wv = *(const float4*)&sW2[k * 64 + tc2 * 4];
#pragma unroll
            for (int i = 0; i < 4; i++) {
                float a = t_all[(to2 * 4 + i) * 128 + k];
                acc[i][0] += a * wv.x; acc[i][1] += a * wv.y;
                acc[i][2] += a * wv.z; acc[i][3] += a * wv.w;
            }
        }
#pragma unroll
        for (int i = 0; i < 4; i++)
            *(float4*)&s2m[(to2 * 4 + i) * 68 + tc2 * 4] =
                make_float4(fmaxf(acc[i][0], 0.f), fmaxf(acc[i][1], 0.f),
                            fmaxf(acc[i][2], 0.f), fmaxf(acc[i][3], 0.f));
    }
    __syncthreads();

    if (tid < 32) {
        float acc = sb3[0];
#pragma unroll 8
        for (int k = 0; k < 64; k++) acc += s2m[tid * 68 + k] * sW3[k];
        out[b * 32 + tid] = acc;
    }
}

// ---------------- launch ----------------
extern "C" void kernel_launch(void* const* d_in, const int* in_sizes, int n_in,
                              void* d_out, int out_size) {
    const float* x      = (const float*)d_in[0];
    const int*   ei     = (const int*)d_in[1];
    const float* orders = (const float*)d_in[2];
    const int*   batch  = (const int*)d_in[3];
    const float* gW1    = (const float*)d_in[4];
    const float* gb1    = (const float*)d_in[5];
    const float* gW2    = (const float*)d_in[6];
    // gb2 (d_in[7]) intentionally unused: BN cancels the second bias
    const float* gamma  = (const float*)d_in[8];
    const float* beta   = (const float*)d_in[9];
    const float* oW1    = (const float*)d_in[10];
    const float* ob1    = (const float*)d_in[11];
    const float* oW2    = (const float*)d_in[12];
    const float* ob2    = (const float*)d_in[13];
    const float* sW1    = (const float*)d_in[14];
    const float* sb1    = (const float*)d_in[15];
    const float* sW2    = (const float*)d_in[16];
    const float* sb2    = (const float*)d_in[17];
    const float* sW3    = (const float*)d_in[18];
    const float* sb3    = (const float*)d_in[19];
    float* out = (float*)d_out;

    void *p_z2, *p_wimg;
    cudaGetSymbolAddress(&p_z2,   g_z2);
    cudaGetSymbolAddress(&p_wimg, g_wimg);

    size_t head_smem = (size_t)(32 * 512 + 32 * 128 + 32 * 68 + 32 * 33) * 4;
    cudaFuncSetAttribute(k_head, cudaFuncAttributeMaxDynamicSharedMemorySize, (int)head_smem);
    cudaFuncSetAttribute(k_fgemm, cudaFuncAttributeMaxDynamicSharedMemorySize, FG_SMEM);

    k_zero<<<(NN + 1 + 255) / 256, 256>>>();
    k_hist<<<(NE + 255) / 256, 256>>>(ei);
    k_scan<<<1, 1024>>>();
    k_fillcsr<<<(NE + 255) / 256, 256>>>(ei);
    k_prepw<<<(NL * 2 * 16384 + 255) / 256, 256>>>(gW1, gW2);

    for (int l = 0; l < NL; l++) {
        if (l == 0) k_agg<0><<<(NN * 32 + 255) / 256, 256>>>(x);
        else        k_agg<1><<<(NN * 32 + 255) / 256, 256>>>((const float*)p_z2);
        k_fgemm<<<NBLK, 256, FG_SMEM>>>((const __nv_bfloat16*)p_wimg + (size_t)l * 4 * 128 * LDA,
                                        gb1 + l * HD, (float*)p_z2);
        k_stats<<<STAT_BLKS, 256>>>();
        k_finalize<<<1, 128>>>(gamma + l * HD, beta + l * HD);
    }

    k_start<<<(NN + 255) / 256, 256>>>(batch);
    k_pool<<<NB, 128>>>();
    k_head<<<NB, 128, head_smem>>>(orders, oW1, ob1, oW2, ob2,
                                   sW1, sb1, sW2, sb2, sW3, sb3, out);
}

// round 8
// speedup vs baseline: 1.0556x; 1.0542x over previous
#include <cuda_runtime.h>
#include <cuda_bf16.h>
#include <mma.h>
#include <math.h>
#include <stdint.h>

using namespace nvcuda;

#define NN 100000
#define NE 1600000
#define NB 256
#define HD 128
#define NL 3

#define TR 32
#define NT (NN / TR)          // 3125 exact
#define NBLK 148
#define LDA 136               // bf16 smem stride
#define LDSG 132              // f32 staging stride

// smem map for fgemm
#define SM_ABUF 0                         // 2 buffers x (hi 8704 + lo 8704) = 34816
#define SM_W    34816                     // 4 tiles = 139264
#define SM_STG  (34816 + 139264)          // 32*132*4 = 16896
#define FG_SMEM (SM_STG + TR * LDSG * 4)  // 190976

// ---------------- device scratch (zero-initialized at load; kept zero by k_cleanup/finalize) ----------------
__device__ __align__(16) __nv_bfloat16 g_ahi[NN * HD];
__device__ __align__(16) __nv_bfloat16 g_alo[NN * HD];
__device__ float g_z2[NN * HD];
__device__ int   g_rowptr[NN + 1];
__device__ int   g_fill[NN];
__device__ int   g_colsrc[NE];
__device__ float g_stats[2 * HD];
__device__ float g_scale[HD];
__device__ float g_shift[HD];
__device__ float g_graph[NB * 3 * HD];
__device__ int   g_start[NB + 1];
__device__ __align__(16) __nv_bfloat16 g_wimg[NL * 4 * 128 * LDA];

union B8 { uint4 u; __nv_bfloat16 b[8]; };
union B4 { unsigned long long u; __nv_bfloat16 b[4]; };

__device__ __forceinline__ uint32_t smem_u32(const void* p) {
    uint32_t a;
    asm("{ .reg .u64 t; cvta.to.shared.u64 t, %1; cvt.u32.u64 %0, t; }" : "=r"(a) : "l"(p));
    return a;
}
__device__ __forceinline__ void cp16(uint32_t dst, const void* src) {
    asm volatile("cp.async.cg.shared.global [%0], [%1], 16;" :: "r"(dst), "l"(src));
}
__device__ __forceinline__ void cp_commit() { asm volatile("cp.async.commit_group;"); }
__device__ __forceinline__ void cp_wait0()  { asm volatile("cp.async.wait_group 0;"); }

// ---------------- CSR build ----------------
__global__ void k_hist(const int* __restrict__ ei) {
    int e = blockIdx.x * blockDim.x + threadIdx.x;
    if (e < NE) atomicAdd(&g_rowptr[ei[NE + e] + 1], 1);
}

__global__ void k_scan() {
    __shared__ int wsum[32];
    __shared__ int carry;
    int tid = threadIdx.x, lane = tid & 31, wid = tid >> 5;
    if (tid == 0) carry = 0;
    const int NCH = (NN + 1 + 1023) / 1024;
    int nv = g_rowptr[tid];
    __syncthreads();
    for (int ch = 0; ch < NCH; ch++) {
        int v = nv;
        if (ch + 1 < NCH) {
            int gn = (ch + 1) * 1024 + tid;
            nv = (gn <= NN) ? g_rowptr[gn] : 0;
        }
        int x = v;
#pragma unroll
        for (int d = 1; d < 32; d <<= 1) { int y = __shfl_up_sync(0xFFFFFFFFu, x, d); if (lane >= d) x += y; }
        if (lane == 31) wsum[wid] = x;
        __syncthreads();
        if (wid == 0) {
            int y = wsum[lane];
#pragma unroll
            for (int d = 1; d < 32; d <<= 1) { int z = __shfl_up_sync(0xFFFFFFFFu, y, d); if (lane >= d) y += z; }
            wsum[lane] = y;
        }
        __syncthreads();
        if (wid > 0) x += wsum[wid - 1];
        int out = x + carry;
        int gid = ch * 1024 + tid;
        if (gid <= NN) g_rowptr[gid] = out;
        __syncthreads();
        if (tid == 1023) carry = out;
        __syncthreads();
    }
}

__global__ void k_fillcsr(const int* __restrict__ ei) {
    int e = blockIdx.x * blockDim.x + threadIdx.x;
    if (e < NE) {
        int dst = ei[NE + e];
        int pos = g_rowptr[dst] + atomicAdd(&g_fill[dst], 1);
        g_colsrc[pos] = ei[e];
    }
}

// ---------------- weight prep ----------------
__global__ void k_prepw(const float* __restrict__ gW1, const float* __restrict__ gW2) {
    int idx = blockIdx.x * blockDim.x + threadIdx.x;
    if (idx >= NL * 2 * 16384) return;
    int l = idx / 32768;
    int rem = idx - l * 32768;
    int m = rem >> 14;
    int e = rem & 16383;
    int k = e >> 7;
    int n = e & 127;
    float v = (m ? gW2 : gW1)[l * 16384 + k * 128 + n];
    __nv_bfloat16 hi = __float2bfloat16_rn(v);
    __nv_bfloat16 lo = __float2bfloat16_rn(v - __bfloat162float(hi));
    __nv_bfloat16* base = g_wimg + (size_t)(l * 4 + m * 2) * 128 * LDA;
    base[k * LDA + n] = hi;
    base[128 * LDA + k * LDA + n] = lo;
}

// ---------------- aggregation: warp/node, fused BN+ReLU on source, split bf16 output ----------------
__device__ __forceinline__ float4 bnrelu4(float4 v, float4 sc, float4 sf) {
    v.x = fmaxf(v.x * sc.x + sf.x, 0.f);
    v.y = fmaxf(v.y * sc.y + sf.y, 0.f);
    v.z = fmaxf(v.z * sc.z + sf.z, 0.f);
    v.w = fmaxf(v.w * sc.w + sf.w, 0.f);
    return v;
}

template <int APPLY>
__global__ void k_agg(const float* __restrict__ src) {
    int w = (blockIdx.x * blockDim.x + threadIdx.x) >> 5;
    int lane = threadIdx.x & 31;
    if (w >= NN) return;
    float4 sc, sf;
    if (APPLY) {
        sc = *(const float4*)&g_scale[lane * 4];
        sf = *(const float4*)&g_shift[lane * 4];
    }
    const float4* hv = (const float4*)src;
    float4 self = hv[w * 32 + lane];
    float4 acc = APPLY ? bnrelu4(self, sc, sf) : self;
    int e = g_rowptr[w], eend = g_rowptr[w + 1];
    // 8-wide: 8 outstanding row-gathers
    for (; e + 8 <= eend; e += 8) {
        int s[8];
#pragma unroll
        for (int j = 0; j < 8; j++) s[j] = g_colsrc[e + j];
        float4 v[8];
#pragma unroll
        for (int j = 0; j < 8; j++) v[j] = hv[s[j] * 32 + lane];
        if (APPLY) {
#pragma unroll
            for (int j = 0; j < 8; j++) v[j] = bnrelu4(v[j], sc, sf);
        }
        float4 t0, t1;
        t0.x = (v[0].x + v[1].x) + (v[2].x + v[3].x);
        t0.y = (v[0].y + v[1].y) + (v[2].y + v[3].y);
        t0.z = (v[0].z + v[1].z) + (v[2].z + v[3].z);
        t0.w = (v[0].w + v[1].w) + (v[2].w + v[3].w);
        t1.x = (v[4].x + v[5].x) + (v[6].x + v[7].x);
        t1.y = (v[4].y + v[5].y) + (v[6].y + v[7].y);
        t1.z = (v[4].z + v[5].z) + (v[6].z + v[7].z);
        t1.w = (v[4].w + v[5].w) + (v[6].w + v[7].w);
        acc.x += t0.x + t1.x; acc.y += t0.y + t1.y;
        acc.z += t0.z + t1.z; acc.w += t0.w + t1.w;
    }
    for (; e + 4 <= eend; e += 4) {
        int s0 = g_colsrc[e + 0], s1 = g_colsrc[e + 1];
        int s2 = g_colsrc[e + 2], s3 = g_colsrc[e + 3];
        float4 v0 = hv[s0 * 32 + lane];
        float4 v1 = hv[s1 * 32 + lane];
        float4 v2 = hv[s2 * 32 + lane];
        float4 v3 = hv[s3 * 32 + lane];
        if (APPLY) {
            v0 = bnrelu4(v0, sc, sf); v1 = bnrelu4(v1, sc, sf);
            v2 = bnrelu4(v2, sc, sf); v3 = bnrelu4(v3, sc, sf);
        }
        acc.x += (v0.x + v1.x) + (v2.x + v3.x);
        acc.y += (v0.y + v1.y) + (v2.y + v3.y);
        acc.z += (v0.z + v1.z) + (v2.z + v3.z);
        acc.w += (v0.w + v1.w) + (v2.w + v3.w);
    }
    for (; e < eend; e++) {
        int s = g_colsrc[e];
        float4 v = hv[s * 32 + lane];
        if (APPLY) v = bnrelu4(v, sc, sf);
        acc.x += v.x; acc.y += v.y; acc.z += v.z; acc.w += v.w;
    }
    float a4[4] = {acc.x, acc.y, acc.z, acc.w};
    B4 hi, lo;
#pragma unroll
    for (int e2 = 0; e2 < 4; e2++) {
        __nv_bfloat16 h = __float2bfloat16_rn(a4[e2]);
        hi.b[e2] = h;
        lo.b[e2] = __float2bfloat16_rn(a4[e2] - __bfloat162float(h));
    }
    *(unsigned long long*)&g_ahi[w * 128 + lane * 4] = hi.u;
    *(unsigned long long*)&g_alo[w * 128 + lane * 4] = lo.u;
}

// ---------------- fused double GEMM, double-buffered cp.async, fused stats ----------------
typedef wmma::fragment<wmma::matrix_a, 16, 16, 16, __nv_bfloat16, wmma::row_major> FragA;
typedef wmma::fragment<wmma::matrix_b, 16, 16, 16, __nv_bfloat16, wmma::row_major> FragB;
typedef wmma::fragment<wmma::accumulator, 16, 16, 16, float> FragC;

__device__ __forceinline__ void gemm_pass32(const __nv_bfloat16* Ahi, const __nv_bfloat16* Alo,
                                            const __nv_bfloat16* Whi, const __nv_bfloat16* Wlo,
                                            FragC c[2], int wy, int wx) {
    wmma::fill_fragment(c[0], 0.f);
    wmma::fill_fragment(c[1], 0.f);
#pragma unroll
    for (int kk = 0; kk < 8; kk++) {
        FragA ahi, alo;
        wmma::load_matrix_sync(ahi, Ahi + (wy * 16) * LDA + kk * 16, LDA);
        wmma::load_matrix_sync(alo, Alo + (wy * 16) * LDA + kk * 16, LDA);
#pragma unroll
        for (int j = 0; j < 2; j++) {
            FragB bhi, blo;
            wmma::load_matrix_sync(bhi, Whi + kk * 16 * LDA + wx * 32 + j * 16, LDA);
            wmma::load_matrix_sync(blo, Wlo + kk * 16 * LDA + wx * 32 + j * 16, LDA);
            wmma::mma_sync(c[j], ahi, bhi, c[j]);
            wmma::mma_sync(c[j], ahi, blo, c[j]);
            wmma::mma_sync(c[j], alo, bhi, c[j]);
        }
    }
}

__device__ __forceinline__ void prefetchA(uint32_t buf_base, int t, int tid) {
#pragma unroll
    for (int i = 0; i < 4; i++) {
        int idx = tid + i * 256;
        int p = idx >> 9;
        int rem = idx & 511;
        int r = rem >> 4, k = rem & 15;
        const __nv_bfloat16* srcp = (p ? g_alo : g_ahi) + (size_t)(t * TR + r) * 128 + k * 8;
        uint32_t dst = buf_base + p * 8704 + r * 272 + k * 16;
        cp16(dst, srcp);
    }
    cp_commit();
}

__global__ void __launch_bounds__(256, 1)
k_fgemm(const __nv_bfloat16* __restrict__ wimg, const float* __restrict__ b1,
        float* __restrict__ Z2) {
    extern __shared__ char sh[];
    uint32_t sbase = smem_u32(sh);
    __nv_bfloat16* Wt = (__nv_bfloat16*)(sh + SM_W);
    float* stg = (float*)(sh + SM_STG);
    int tid = threadIdx.x;
    int bid = blockIdx.x;
    int w = tid >> 5, wy = w >> 2, wx = w & 3;
    int scol = tid & 127, shalf = tid >> 7;
    float s_acc = 0.f, q_acc = 0.f;

    {   // weights: 139264 B = 8704 uint4
        const uint4* wg = (const uint4*)wimg;
        uint4* wd = (uint4*)Wt;
#pragma unroll
        for (int i = 0; i < 34; i++) {
            int idx = tid + i * 256;
            if (idx < 8704) wd[idx] = wg[idx];
        }
    }

    prefetchA(sbase + SM_ABUF, bid, tid);

    int buf = 0;
    for (int t = bid; t < NT; t += NBLK, buf ^= 1) {
        cp_wait0();
        __syncthreads();
        int tn = t + NBLK;
        if (tn < NT) prefetchA(sbase + SM_ABUF + (buf ^ 1) * 17408, tn, tid);

        __nv_bfloat16* Ahi = (__nv_bfloat16*)(sh + SM_ABUF + buf * 17408);
        __nv_bfloat16* Alo = Ahi + 4352;

        FragC c[2];
        gemm_pass32(Ahi, Alo, Wt, Wt + 128 * LDA, c, wy, wx);
        wmma::store_matrix_sync(stg + (wy * 16) * LDSG + wx * 32, c[0], LDSG, wmma::mem_row_major);
        wmma::store_matrix_sync(stg + (wy * 16) * LDSG + wx * 32 + 16, c[1], LDSG, wmma::mem_row_major);
        __syncthreads();

#pragma unroll
        for (int ii = 0; ii < 2; ii++) {
            int i = tid + ii * 256;
            int r = i >> 4, c0 = (i & 15) << 3;
            B8 hi, lo;
#pragma unroll
            for (int e = 0; e < 8; e++) {
                float v = fmaxf(stg[r * LDSG + c0 + e] + b1[c0 + e], 0.f);
                __nv_bfloat16 h = __float2bfloat16_rn(v);
                hi.b[e] = h;
                lo.b[e] = __float2bfloat16_rn(v - __bfloat162float(h));
            }
            *(uint4*)&Ahi[r * LDA + c0] = hi.u;
            *(uint4*)&Alo[r * LDA + c0] = lo.u;
        }
        __syncthreads();

        gemm_pass32(Ahi, Alo, Wt + 2 * 128 * LDA, Wt + 3 * 128 * LDA, c, wy, wx);
        wmma::store_matrix_sync(stg + (wy * 16) * LDSG + wx * 32, c[0], LDSG, wmma::mem_row_major);
        wmma::store_matrix_sync(stg + (wy * 16) * LDSG + wx * 32 + 16, c[1], LDSG, wmma::mem_row_major);
        __syncthreads();

#pragma unroll
        for (int i = 0; i < 4; i++) {
            int idx = tid + i * 256;
            int r = idx >> 5, g = idx & 31;
            float4 v;
            v.x = stg[r * LDSG + g * 4 + 0];
            v.y = stg[r * LDSG + g * 4 + 1];
            v.z = stg[r * LDSG + g * 4 + 2];
            v.w = stg[r * LDSG + g * 4 + 3];
            *(float4*)&Z2[(size_t)(t * TR + r) * 128 + g * 4] = v;
        }
#pragma unroll
        for (int r = 0; r < TR / 2; r++) {
            float v = stg[(shalf + r * 2) * LDSG + scol];
            s_acc += v; q_acc += v * v;
        }
    }

    atomicAdd(&g_stats[scol], s_acc);
    atomicAdd(&g_stats[128 + scol], q_acc);
}

__global__ void k_finalize(const float* __restrict__ gamma, const float* __restrict__ beta) {
    int j = threadIdx.x;
    float mu = g_stats[j] * (1.0f / NN);
    float var = g_stats[128 + j] * (1.0f / NN) - mu * mu;
    float a = gamma[j] * rsqrtf(var + 1e-5f);
    g_scale[j] = a;
    g_shift[j] = beta[j] - mu * a;
    g_stats[j] = 0.f;
    g_stats[128 + j] = 0.f;
}

// ---------------- pooling (applies final BN) ----------------
__global__ void k_start(const int* __restrict__ batch) {
    int n = blockIdx.x * blockDim.x + threadIdx.x;
    if (n >= NN) return;
    int b = batch[n];
    if (n == 0) { for (int i = 0; i <= b; i++) g_start[i] = 0; }
    else {
        int p = batch[n - 1];
        for (int i = p + 1; i <= b; i++) g_start[i] = n;
    }
    if (n == NN - 1) { for (int i = b + 1; i <= NB; i++) g_start[i] = NN; }
}

__global__ void k_pool() {
    int b = blockIdx.x, j = threadIdx.x;
    int s = g_start[b], e = g_start[b + 1];
    float sc = g_scale[j], sf = g_shift[j];
    float sum = 0.f, mx = -3.402823466e38f;
    int n = s;
    for (; n + 2 <= e; n += 2) {
        float v0 = g_z2[(size_t)n * HD + j] * sc + sf;
        float v1 = g_z2[(size_t)(n + 1) * HD + j] * sc + sf;
        sum += v0 + v1;
        mx = fmaxf(mx, fmaxf(v0, v1));
    }
    for (; n < e; n++) {
        float v = g_z2[(size_t)n * HD + j] * sc + sf;
        sum += v; mx = fmaxf(mx, v);
    }
    int cnt = e - s;
    g_graph[b * 384 + j]       = cnt ? sum / (float)cnt : 0.f;
    g_graph[b * 384 + 128 + j] = cnt ? mx : 0.f;
    g_graph[b * 384 + 256 + j] = sum;
}

// ---------------- head ----------------
__global__ void k_head(const float* __restrict__ orders,
                       const float* __restrict__ oW1, const float* __restrict__ ob1,
                       const float* __restrict__ oW2, const float* __restrict__ ob2,
                       const float* __restrict__ sW1, const float* __restrict__ sb1,
                       const float* __restrict__ sW2, const float* __restrict__ sb2,
                       const float* __restrict__ sW3, const float* __restrict__ sb3,
                       float* __restrict__ out) {
    extern __shared__ float fsh[];
    float* comb  = fsh;                      // 32*512
    float* t_all = comb + 32 * 512;          // 32*128
    float* s2m   = t_all + 32 * 128;         // 32*68
    float* ords  = s2m + 32 * 68;            // 32*33
    int b = blockIdx.x, tid = threadIdx.x;

    for (int idx = tid; idx < 32 * 384; idx += 128) {
        int o = idx / 384, k = idx - o * 384;
        comb[o * 512 + k] = g_graph[b * 384 + k];
    }
    for (int idx = tid; idx < 32 * 32; idx += 128) {
        int o = idx >> 5, k = idx & 31;
        ords[o * 33 + k] = orders[(b * 32 + o) * 32 + k];
    }
    __syncthreads();

    int tcol = tid & 31, tord = tid >> 5;

    {   // t = relu(ords @ oW1 + ob1)
        float4 bc = *(const float4*)&ob1[tcol * 4];
        float acc[8][4];
#pragma unroll
        for (int i = 0; i < 8; i++) { acc[i][0] = bc.x; acc[i][1] = bc.y; acc[i][2] = bc.z; acc[i][3] = bc.w; }
#pragma unroll
        for (int k = 0; k < 32; k++) {
            float4 wv = *(const float4*)&oW1[k * 128 + tcol * 4];
#pragma unroll
            for (int i = 0; i < 8; i++) {
                float a = ords[(tord * 8 + i) * 33 + k];
                acc[i][0] += a * wv.x; acc[i][1] += a * wv.y;
                acc[i][2] += a * wv.z; acc[i][3] += a * wv.w;
            }
        }
#pragma unroll
        for (int i = 0; i < 8; i++)
            *(float4*)&t_all[(tord * 8 + i) * 128 + tcol * 4] =
                make_float4(fmaxf(acc[i][0], 0.f), fmaxf(acc[i][1], 0.f),
                            fmaxf(acc[i][2], 0.f), fmaxf(acc[i][3], 0.f));
    }
    __syncthreads();

    {   // oe = t @ oW2 + ob2 -> comb[:,384:]
        float4 bc = *(const float4*)&ob2[tcol * 4];
        float acc[8][4];
#pragma unroll
        for (int i = 0; i < 8; i++) { acc[i][0] = bc.x; acc[i][1] = bc.y; acc[i][2] = bc.z; acc[i][3] = bc.w; }
#pragma unroll 4
        for (int k = 0; k < 128; k++) {
            float4 wv = *(const float4*)&oW2[k * 128 + tcol * 4];
#pragma unroll
            for (int i = 0; i < 8; i++) {
                float a = t_all[(tord * 8 + i) * 128 + k];
                acc[i][0] += a * wv.x; acc[i][1] += a * wv.y;
                acc[i][2] += a * wv.z; acc[i][3] += a * wv.w;
            }
        }
        __syncthreads();
#pragma unroll
        for (int i = 0; i < 8; i++)
            *(float4*)&comb[(tord * 8 + i) * 512 + 384 + tcol * 4] =
                make_float4(acc[i][0], acc[i][1], acc[i][2], acc[i][3]);
    }
    __syncthreads();

    {   // s1 = relu(comb @ sW1 + sb1)
        float4 bc = *(const float4*)&sb1[tcol * 4];
        float acc[8][4];
#pragma unroll
        for (int i = 0; i < 8; i++) { acc[i][0] = bc.x; acc[i][1] = bc.y; acc[i][2] = bc.z; acc[i][3] = bc.w; }
#pragma unroll 4
        for (int k = 0; k < 512; k++) {
            float4 wv = *(const float4*)&sW1[k * 128 + tcol * 4];
#pragma unroll
            for (int i = 0; i < 8; i++) {
                float a = comb[(tord * 8 + i) * 512 + k];
                acc[i][0] += a * wv.x; acc[i][1] += a * wv.y;
                acc[i][2] += a * wv.z; acc[i][3] += a * wv.w;
            }
        }
#pragma unroll
        for (int i = 0; i < 8; i++)
            *(float4*)&t_all[(tord * 8 + i) * 128 + tcol * 4] =
                make_float4(fmaxf(acc[i][0], 0.f), fmaxf(acc[i][1], 0.f),
                            fmaxf(acc[i][2], 0.f), fmaxf(acc[i][3], 0.f));
    }
    __syncthreads();

    {   // s2 = relu(s1 @ sW2 + sb2)
        int tc2 = tid & 15, to2 = tid >> 4;
        float4 bc = *(const float4*)&sb2[tc2 * 4];
        float acc[4][4];
#pragma unroll
        for (int i = 0; i < 4; i++) { acc[i][0] = bc.x; acc[i][1] = bc.y; acc[i][2] = bc.z; acc[i][3] = bc.w; }
#pragma unroll 4
        for (int k = 0; k < 128; k++) {
            float4 wv = *(const float4*)&sW2[k * 64 + tc2 * 4];
#pragma unroll
            for (int i = 0; i < 4; i++) {
                float a = t_all[(to2 * 4 + i) * 128 + k];
                acc[i][0] += a * wv.x; acc[i][1] += a * wv.y;
                acc[i][2] += a * wv.z; acc[i][3] += a * wv.w;
            }
        }
#pragma unroll
        for (int i = 0; i < 4; i++)
            *(float4*)&s2m[(to2 * 4 + i) * 68 + tc2 * 4] =
                make_float4(fmaxf(acc[i][0], 0.f), fmaxf(acc[i][1], 0.f),
                            fmaxf(acc[i][2], 0.f), fmaxf(acc[i][3], 0.f));
    }
    __syncthreads();

    if (tid < 32) {
        float acc = sb3[0];
#pragma unroll 8
        for (int k = 0; k < 64; k++) acc += s2m[tid * 68 + k] * sW3[k];
        out[b * 32 + tid] = acc;
    }
}

// ---------------- end-of-launch cleanup: restore zero invariants for next replay ----------------
__global__ void k_cleanup() {
    int i = blockIdx.x * blockDim.x + threadIdx.x;
    if (i <= NN) g_rowptr[i] = 0;
    if (i < NN)  g_fill[i] = 0;
}

// ---------------- launch ----------------
extern "C" void kernel_launch(void* const* d_in, const int* in_sizes, int n_in,
                              void* d_out, int out_size) {
    const float* x      = (const float*)d_in[0];
    const int*   ei     = (const int*)d_in[1];
    const float* orders = (const float*)d_in[2];
    const int*   batch  = (const int*)d_in[3];
    const float* gW1    = (const float*)d_in[4];
    const float* gb1    = (const float*)d_in[5];
    const float* gW2    = (const float*)d_in[6];
    // gb2 (d_in[7]) unused: BN cancels the second bias
    const float* gamma  = (const float*)d_in[8];
    const float* beta   = (const float*)d_in[9];
    const float* oW1    = (const float*)d_in[10];
    const float* ob1    = (const float*)d_in[11];
    const float* oW2    = (const float*)d_in[12];
    const float* ob2    = (const float*)d_in[13];
    const float* sW1    = (const float*)d_in[14];
    const float* sb1    = (const float*)d_in[15];
    const float* sW2    = (const float*)d_in[16];
    const float* sb2    = (const float*)d_in[17];
    const float* sW3    = (const float*)d_in[18];
    const float* sb3    = (const float*)d_in[19];
    float* out = (float*)d_out;

    void *p_z2, *p_wimg;
    cudaGetSymbolAddress(&p_z2,   g_z2);
    cudaGetSymbolAddress(&p_wimg, g_wimg);

    size_t head_smem = (size_t)(32 * 512 + 32 * 128 + 32 * 68 + 32 * 33) * 4;
    cudaFuncSetAttribute(k_head, cudaFuncAttributeMaxDynamicSharedMemorySize, (int)head_smem);
    cudaFuncSetAttribute(k_fgemm, cudaFuncAttributeMaxDynamicSharedMemorySize, FG_SMEM);

    // rowptr/fill/stats are zero here: zero-initialized at load, re-zeroed by
    // k_cleanup / k_finalize at the end of every launch (deterministic).
    k_hist<<<(NE + 255) / 256, 256>>>(ei);            // 1
    k_scan<<<1, 1024>>>();                            // 2
    k_fillcsr<<<(NE + 255) / 256, 256>>>(ei);         // 3
    k_agg<0><<<(NN * 32 + 255) / 256, 256>>>(x);      // 4  <- profiled
    k_prepw<<<(NL * 2 * 16384 + 255) / 256, 256>>>(gW1, gW2);   // 5

    for (int l = 0; l < NL; l++) {
        if (l > 0) k_agg<1><<<(NN * 32 + 255) / 256, 256>>>((const float*)p_z2);
        k_fgemm<<<NBLK, 256, FG_SMEM>>>((const __nv_bfloat16*)p_wimg + (size_t)l * 4 * 128 * LDA,
                                        gb1 + l * HD, (float*)p_z2);
        k_finalize<<<1, 128>>>(gamma + l * HD, beta + l * HD);
    }

    k_start<<<(NN + 255) / 256, 256>>>(batch);
    k_pool<<<NB, 128>>>();
    k_head<<<NB, 128, head_smem>>>(orders, oW1, ob1, oW2, ob2,
                                   sW1, sb1, sW2, sb2, sW3, sb3, out);
    k_cleanup<<<(NN + 1 + 255) / 256, 256>>>();
}

// round 9
// speedup vs baseline: 1.1487x; 1.0882x over previous
#include <cuda_runtime.h>
#include <cuda_bf16.h>
#include <math.h>
#include <stdint.h>

#define NN 100000
#define NE 1600000
#define NB 256
#define HD 128
#define NL 3

#define NBLK 148
#define TROWS 128                      // block tile rows (8 warps x 16)
#define NT ((NN + TROWS - 1) / TROWS)  // 782
#define LDW 136                        // bf16 stride of weight tiles (272 B rows)
#define WTILE 34816                    // bytes per 128x136 bf16 weight tile

// fgemm smem map
#define STRIP_PL 4352                  // bytes per plane strip (16*136*2)
#define STRIP_SZ 8704                  // hi+lo
#define SM_A   0                       // 8 warps * 8704 = 69632
#define SM_W   69632                   // 4 tiles = 139264
#define SM_B1  (69632 + 139264)        // 512 B bias
#define FG_SMEM (SM_B1 + 512)          // 209408

// ---------------- device scratch ----------------
__device__ __align__(16) __nv_bfloat16 g_ahi[NN * HD];
__device__ __align__(16) __nv_bfloat16 g_alo[NN * HD];
__device__ float g_z2[NN * HD];
__device__ int   g_rowptr[NN + 1];
__device__ int   g_fill[NN];
__device__ int   g_colsrc[NE];
__device__ float g_stats[2 * HD];
__device__ float g_scale[HD];
__device__ float g_shift[HD];
__device__ float g_graph[NB * 3 * HD];
__device__ int   g_start[NB + 1];
__device__ __align__(16) __nv_bfloat16 g_wimg[NL * 4 * 128 * LDW];

union B4 { unsigned long long u; __nv_bfloat16 b[4]; };
union B2 { uint32_t u; __nv_bfloat16 b[2]; };

__device__ __forceinline__ uint32_t smem_u32(const void* p) {
    uint32_t a;
    asm("{ .reg .u64 t; cvta.to.shared.u64 t, %1; cvt.u32.u64 %0, t; }" : "=r"(a) : "l"(p));
    return a;
}
__device__ __forceinline__ void cp16p(uint32_t dst, const void* src, int sz) {
    asm volatile("cp.async.cg.shared.global [%0], [%1], 16, %2;" :: "r"(dst), "l"(src), "r"(sz));
}
__device__ __forceinline__ void cp_commit() { asm volatile("cp.async.commit_group;"); }
__device__ __forceinline__ void cp_wait0()  { asm volatile("cp.async.wait_group 0;"); }

__device__ __forceinline__ void ldm_x4(uint32_t* r, uint32_t addr) {
    asm volatile("ldmatrix.sync.aligned.m8n8.x4.shared.b16 {%0,%1,%2,%3}, [%4];"
                 : "=r"(r[0]), "=r"(r[1]), "=r"(r[2]), "=r"(r[3]) : "r"(addr));
}
__device__ __forceinline__ void ldm_x4t(uint32_t* r, uint32_t addr) {
    asm volatile("ldmatrix.sync.aligned.m8n8.x4.trans.shared.b16 {%0,%1,%2,%3}, [%4];"
                 : "=r"(r[0]), "=r"(r[1]), "=r"(r[2]), "=r"(r[3]) : "r"(addr));
}
__device__ __forceinline__ void mma16816(float* d, const uint32_t* a, uint32_t b0, uint32_t b1) {
    asm volatile("mma.sync.aligned.m16n8k16.row.col.f32.bf16.bf16.f32 "
                 "{%0,%1,%2,%3}, {%4,%5,%6,%7}, {%8,%9}, {%0,%1,%2,%3};"
                 : "+f"(d[0]), "+f"(d[1]), "+f"(d[2]), "+f"(d[3])
                 : "r"(a[0]), "r"(a[1]), "r"(a[2]), "r"(a[3]), "r"(b0), "r"(b1));
}

// ---------------- CSR build ----------------
__global__ void k_hist(const int* __restrict__ ei) {
    int e = blockIdx.x * blockDim.x + threadIdx.x;
    if (e < NE) atomicAdd(&g_rowptr[ei[NE + e] + 1], 1);
}

__global__ void k_scan() {
    __shared__ int wsum[32];
    __shared__ int carry;
    int tid = threadIdx.x, lane = tid & 31, wid = tid >> 5;
    if (tid == 0) carry = 0;
    const int NCH = (NN + 1 + 1023) / 1024;
    int nv = g_rowptr[tid];
    __syncthreads();
    for (int ch = 0; ch < NCH; ch++) {
        int v = nv;
        if (ch + 1 < NCH) {
            int gn = (ch + 1) * 1024 + tid;
            nv = (gn <= NN) ? g_rowptr[gn] : 0;
        }
        int x = v;
#pragma unroll
        for (int d = 1; d < 32; d <<= 1) { int y = __shfl_up_sync(0xFFFFFFFFu, x, d); if (lane >= d) x += y; }
        if (lane == 31) wsum[wid] = x;
        __syncthreads();
        if (wid == 0) {
            int y = wsum[lane];
#pragma unroll
            for (int d = 1; d < 32; d <<= 1) { int z = __shfl_up_sync(0xFFFFFFFFu, y, d); if (lane >= d) y += z; }
            wsum[lane] = y;
        }
        __syncthreads();
        if (wid > 0) x += wsum[wid - 1];
        int out = x + carry;
        int gid = ch * 1024 + tid;
        if (gid <= NN) g_rowptr[gid] = out;
        __syncthreads();
        if (tid == 1023) carry = out;
        __syncthreads();
    }
}

__global__ void k_fillcsr(const int* __restrict__ ei) {
    int e = blockIdx.x * blockDim.x + threadIdx.x;
    if (e < NE) {
        int dst = ei[NE + e];
        int pos = g_rowptr[dst] + atomicAdd(&g_fill[dst], 1);
        g_colsrc[pos] = ei[e];
    }
}

// ---------------- weight prep ([k][n] row-major, stride 136) ----------------
__global__ void k_prepw(const float* __restrict__ gW1, const float* __restrict__ gW2) {
    int idx = blockIdx.x * blockDim.x + threadIdx.x;
    if (idx >= NL * 2 * 16384) return;
    int l = idx / 32768;
    int rem = idx - l * 32768;
    int m = rem >> 14;
    int e = rem & 16383;
    int k = e >> 7;
    int n = e & 127;
    float v = (m ? gW2 : gW1)[l * 16384 + k * 128 + n];
    __nv_bfloat16 hi = __float2bfloat16_rn(v);
    __nv_bfloat16 lo = __float2bfloat16_rn(v - __bfloat162float(hi));
    __nv_bfloat16* base = g_wimg + (size_t)(l * 4 + m * 2) * 128 * LDW;
    base[k * LDW + n] = hi;
    base[128 * LDW + k * LDW + n] = lo;
}

// ---------------- aggregation (round-8 version) ----------------
__device__ __forceinline__ float4 bnrelu4(float4 v, float4 sc, float4 sf) {
    v.x = fmaxf(v.x * sc.x + sf.x, 0.f);
    v.y = fmaxf(v.y * sc.y + sf.y, 0.f);
    v.z = fmaxf(v.z * sc.z + sf.z, 0.f);
    v.w = fmaxf(v.w * sc.w + sf.w, 0.f);
    return v;
}

template <int APPLY>
__global__ void k_agg(const float* __restrict__ src) {
    int w = (blockIdx.x * blockDim.x + threadIdx.x) >> 5;
    int lane = threadIdx.x & 31;
    if (w >= NN) return;
    float4 sc, sf;
    if (APPLY) {
        sc = *(const float4*)&g_scale[lane * 4];
        sf = *(const float4*)&g_shift[lane * 4];
    }
    const float4* hv = (const float4*)src;
    float4 self = hv[w * 32 + lane];
    float4 acc = APPLY ? bnrelu4(self, sc, sf) : self;
    int e = g_rowptr[w], eend = g_rowptr[w + 1];
    for (; e + 8 <= eend; e += 8) {
        int s[8];
#pragma unroll
        for (int j = 0; j < 8; j++) s[j] = g_colsrc[e + j];
        float4 v[8];
#pragma unroll
        for (int j = 0; j < 8; j++) v[j] = hv[s[j] * 32 + lane];
        if (APPLY) {
#pragma unroll
            for (int j = 0; j < 8; j++) v[j] = bnrelu4(v[j], sc, sf);
        }
        acc.x += ((v[0].x + v[1].x) + (v[2].x + v[3].x)) + ((v[4].x + v[5].x) + (v[6].x + v[7].x));
        acc.y += ((v[0].y + v[1].y) + (v[2].y + v[3].y)) + ((v[4].y + v[5].y) + (v[6].y + v[7].y));
        acc.z += ((v[0].z + v[1].z) + (v[2].z + v[3].z)) + ((v[4].z + v[5].z) + (v[6].z + v[7].z));
        acc.w += ((v[0].w + v[1].w) + (v[2].w + v[3].w)) + ((v[4].w + v[5].w) + (v[6].w + v[7].w));
    }
    for (; e < eend; e++) {
        int s = g_colsrc[e];
        float4 v = hv[s * 32 + lane];
        if (APPLY) v = bnrelu4(v, sc, sf);
        acc.x += v.x; acc.y += v.y; acc.z += v.z; acc.w += v.w;
    }
    float a4[4] = {acc.x, acc.y, acc.z, acc.w};
    B4 hi, lo;
#pragma unroll
    for (int e2 = 0; e2 < 4; e2++) {
        __nv_bfloat16 h = __float2bfloat16_rn(a4[e2]);
        hi.b[e2] = h;
        lo.b[e2] = __float2bfloat16_rn(a4[e2] - __bfloat162float(h));
    }
    *(unsigned long long*)&g_ahi[w * 128 + lane * 4] = hi.u;
    *(unsigned long long*)&g_alo[w * 128 + lane * 4] = lo.u;
}

// ---------------- barrier-free fused double GEMM (raw mma.sync, register-chained) ----------------
__global__ void __launch_bounds__(256, 1)
k_fgemm(const __nv_bfloat16* __restrict__ wimg, const float* __restrict__ b1,
        float* __restrict__ Z2) {
    extern __shared__ char sh[];
    uint32_t sb = smem_u32(sh);
    int tid = threadIdx.x;
    int lane = tid & 31, w = tid >> 5;
    int g = lane >> 2, tg = lane & 3;

    {   // W image -> smem (8704 uint4)
        const uint4* wg = (const uint4*)wimg;
        uint4* wd = (uint4*)(sh + SM_W);
#pragma unroll
        for (int i = 0; i < 34; i++) {
            int idx = tid + i * 256;
            if (idx < 8704) wd[idx] = wg[idx];
        }
        if (tid < 128) ((float*)(sh + SM_B1))[tid] = b1[tid];
    }
    __syncthreads();

    const float* b1s = (const float*)(sh + SM_B1);
    uint32_t astrip = sb + SM_A + w * STRIP_SZ;   // hi plane; lo at +STRIP_PL
    uint32_t wbase = sb + SM_W;

    // ldmatrix lane addressing (constant per thread)
    uint32_t a_row = lane & 15;
    uint32_t a_coff = ((lane >> 4) << 3) * 2;         // +8 cols (bytes) for upper half-lanes
    uint32_t b_row = lane & 15;
    uint32_t b_coff = ((lane >> 4) << 3) * 2;

    for (int t = blockIdx.x; t < NT; t += NBLK) {
        int row0 = t * TROWS + w * 16;

        // prefetch this warp's 16-row strip, both planes, zfill OOB
#pragma unroll
        for (int i = 0; i < 16; i++) {
            int idx = lane + i * 32;
            int pl = idx >> 8;
            int rem = idx & 255;
            int r = rem >> 4, ch = rem & 15;
            int gr = row0 + r;
            const __nv_bfloat16* srcp = (pl ? g_alo : g_ahi) + (size_t)gr * 128 + ch * 8;
            int sz = (gr < NN) ? 16 : 0;
            cp16p(astrip + pl * STRIP_PL + r * 272 + ch * 16, srcp, sz);
        }
        cp_commit();
        cp_wait0();
        __syncwarp();

        // ---- GEMM1: acc[j] (16 n8-tiles) = A(16x128) @ W1(128x128), 3-term bf16 split ----
        float acc[16][4];
#pragma unroll
        for (int j = 0; j < 16; j++) { acc[j][0] = 0.f; acc[j][1] = 0.f; acc[j][2] = 0.f; acc[j][3] = 0.f; }

#pragma unroll
        for (int kk = 0; kk < 8; kk++) {
            uint32_t ah[4], al[4];
            uint32_t aaddr = astrip + a_row * 272 + (uint32_t)(kk * 32) + a_coff;
            ldm_x4(ah, aaddr);
            ldm_x4(al, aaddr + STRIP_PL);
#pragma unroll
            for (int jp = 0; jp < 8; jp++) {
                uint32_t boff = b_row * 272 + (uint32_t)(kk * 16 * 272) + (uint32_t)(jp * 32) + b_coff;
                uint32_t bh[4], bl[4];
                ldm_x4t(bh, wbase + boff);            // W1hi
                ldm_x4t(bl, wbase + WTILE + boff);    // W1lo
                mma16816(acc[2 * jp],     ah, bh[0], bh[1]);
                mma16816(acc[2 * jp],     ah, bl[0], bl[1]);
                mma16816(acc[2 * jp],     al, bh[0], bh[1]);
                mma16816(acc[2 * jp + 1], ah, bh[2], bh[3]);
                mma16816(acc[2 * jp + 1], ah, bl[2], bl[3]);
                mma16816(acc[2 * jp + 1], al, bh[2], bh[3]);
            }
        }

        // ---- convert: z1 = relu(acc + b1) -> bf16 hi/lo A-fragments for GEMM2 (in registers) ----
        uint32_t a2h[8][4], a2l[8][4];
#pragma unroll
        for (int j2 = 0; j2 < 8; j2++) {
#pragma unroll
            for (int half = 0; half < 2; half++) {
                int tile = 2 * j2 + half;
                float bb0 = b1s[tile * 8 + 2 * tg];
                float bb1 = b1s[tile * 8 + 2 * tg + 1];
                float z0 = fmaxf(acc[tile][0] + bb0, 0.f);
                float z1 = fmaxf(acc[tile][1] + bb1, 0.f);
                float z2v = fmaxf(acc[tile][2] + bb0, 0.f);
                float z3 = fmaxf(acc[tile][3] + bb1, 0.f);
                B2 h01, h23, l01, l23;
                __nv_bfloat16 h;
                h = __float2bfloat16_rn(z0);  h01.b[0] = h; l01.b[0] = __float2bfloat16_rn(z0 - __bfloat162float(h));
                h = __float2bfloat16_rn(z1);  h01.b[1] = h; l01.b[1] = __float2bfloat16_rn(z1 - __bfloat162float(h));
                h = __float2bfloat16_rn(z2v); h23.b[0] = h; l23.b[0] = __float2bfloat16_rn(z2v - __bfloat162float(h));
                h = __float2bfloat16_rn(z3);  h23.b[1] = h; l23.b[1] = __float2bfloat16_rn(z3 - __bfloat162float(h));
                a2h[j2][2 * half]     = h01.u;
                a2h[j2][2 * half + 1] = h23.u;
                a2l[j2][2 * half]     = l01.u;
                a2l[j2][2 * half + 1] = l23.u;
            }
        }

        // ---- GEMM2: acc2 = z1(16x128) @ W2(128x128), 3-term ----
        float acc2[16][4];
#pragma unroll
        for (int j = 0; j < 16; j++) { acc2[j][0] = 0.f; acc2[j][1] = 0.f; acc2[j][2] = 0.f; acc2[j][3] = 0.f; }

#pragma unroll
        for (int kk = 0; kk < 8; kk++) {
#pragma unroll
            for (int jp = 0; jp < 8; jp++) {
                uint32_t boff = b_row * 272 + (uint32_t)(kk * 16 * 272) + (uint32_t)(jp * 32) + b_coff;
                uint32_t bh[4], bl[4];
                ldm_x4t(bh, wbase + 2 * WTILE + boff);   // W2hi
                ldm_x4t(bl, wbase + 3 * WTILE + boff);   // W2lo
                mma16816(acc2[2 * jp],     a2h[kk], bh[0], bh[1]);
                mma16816(acc2[2 * jp],     a2h[kk], bl[0], bl[1]);
                mma16816(acc2[2 * jp],     a2l[kk], bh[0], bh[1]);
                mma16816(acc2[2 * jp + 1], a2h[kk], bh[2], bh[3]);
                mma16816(acc2[2 * jp + 1], a2h[kk], bl[2], bl[3]);
                mma16816(acc2[2 * jp + 1], a2l[kk], bh[2], bh[3]);
            }
        }

        // ---- z2 store (no bias: BN cancels it) ----
        int r1 = row0 + g, r2 = row0 + g + 8;
        bool l1 = r1 < NN, l2 = r2 < NN;
#pragma unroll
        for (int j = 0; j < 16; j++) {
            int col = j * 8 + 2 * tg;
            if (l1) *(float2*)&Z2[(size_t)r1 * 128 + col] = make_float2(acc2[j][0], acc2[j][1]);
            if (l2) *(float2*)&Z2[(size_t)r2 * 128 + col] = make_float2(acc2[j][2], acc2[j][3]);
        }
    }
}

// ---------------- column stats over z2raw ----------------
#define STAT_BLKS 250
#define STAT_CHUNK (NN / STAT_BLKS)   // 400
__global__ void k_stats() {
    int col = threadIdx.x & 127, half = threadIdx.x >> 7;
    int r0 = blockIdx.x * STAT_CHUNK;
    float s = 0.f, q = 0.f;
    for (int r = r0 + half; r < r0 + STAT_CHUNK; r += 2) {
        float v = g_z2[(size_t)r * 128 + col];
        s += v; q += v * v;
    }
    atomicAdd(&g_stats[col], s);
    atomicAdd(&g_stats[128 + col], q);
}

__global__ void k_finalize(const float* __restrict__ gamma, const float* __restrict__ beta) {
    int j = threadIdx.x;
    float mu = g_stats[j] * (1.0f / NN);
    float var = g_stats[128 + j] * (1.0f / NN) - mu * mu;
    float a = gamma[j] * rsqrtf(var + 1e-5f);
    g_scale[j] = a;
    g_shift[j] = beta[j] - mu * a;
    g_stats[j] = 0.f;
    g_stats[128 + j] = 0.f;
}

// ---------------- pooling (applies final BN) ----------------
__global__ void k_start(const int* __restrict__ batch) {
    int n = blockIdx.x * blockDim.x + threadIdx.x;
    if (n >= NN) return;
    int b = batch[n];
    if (n == 0) { for (int i = 0; i <= b; i++) g_start[i] = 0; }
    else {
        int p = batch[n - 1];
        for (int i = p + 1; i <= b; i++) g_start[i] = n;
    }
    if (n == NN - 1) { for (int i = b + 1; i <= NB; i++) g_start[i] = NN; }
}

__global__ void k_pool() {
    int b = blockIdx.x, j = threadIdx.x;
    int s = g_start[b], e = g_start[b + 1];
    float sc = g_scale[j], sf = g_shift[j];
    float sum = 0.f, mx = -3.402823466e38f;
    int n = s;
    for (; n + 2 <= e; n += 2) {
        float v0 = g_z2[(size_t)n * HD + j] * sc + sf;
        float v1 = g_z2[(size_t)(n + 1) * HD + j] * sc + sf;
        sum += v0 + v1;
        mx = fmaxf(mx, fmaxf(v0, v1));
    }
    for (; n < e; n++) {
        float v = g_z2[(size_t)n * HD + j] * sc + sf;
        sum += v; mx = fmaxf(mx, v);
    }
    int cnt = e - s;
    g_graph[b * 384 + j]       = cnt ? sum / (float)cnt : 0.f;
    g_graph[b * 384 + 128 + j] = cnt ? mx : 0.f;
    g_graph[b * 384 + 256 + j] = sum;
}

// ---------------- head ----------------
__global__ void k_head(const float* __restrict__ orders,
                       const float* __restrict__ oW1, const float* __restrict__ ob1,
                       const float* __restrict__ oW2, const float* __restrict__ ob2,
                       const float* __restrict__ sW1, const float* __restrict__ sb1,
                       const float* __restrict__ sW2, const float* __restrict__ sb2,
                       const float* __restrict__ sW3, const float* __restrict__ sb3,
                       float* __restrict__ out) {
    extern __shared__ float fsh[];
    float* comb  = fsh;                      // 32*512
    float* t_all = comb + 32 * 512;          // 32*128
    float* s2m   = t_all + 32 * 128;         // 32*68
    float* ords  = s2m + 32 * 68;            // 32*33
    int b = blockIdx.x, tid = threadIdx.x;

    for (int idx = tid; idx < 32 * 384; idx += 128) {
        int o = idx / 384, k = idx - o * 384;
        comb[o * 512 + k] = g_graph[b * 384 + k];
    }
    for (int idx = tid; idx < 32 * 32; idx += 128) {
        int o = idx >> 5, k = idx & 31;
        ords[o * 33 + k] = orders[(b * 32 + o) * 32 + k];
    }
    __syncthreads();

    int tcol = tid & 31, tord = tid >> 5;

    {   // t = relu(ords @ oW1 + ob1)
        float4 bc = *(const float4*)&ob1[tcol * 4];
        float acc[8][4];
#pragma unroll
        for (int i = 0; i < 8; i++) { acc[i][0] = bc.x; acc[i][1] = bc.y; acc[i][2] = bc.z; acc[i][3] = bc.w; }
#pragma unroll
        for (int k = 0; k < 32; k++) {
            float4 wv = *(const float4*)&oW1[k * 128 + tcol * 4];
#pragma unroll
            for (int i = 0; i < 8; i++) {
                float a = ords[(tord * 8 + i) * 33 + k];
                acc[i][0] += a * wv.x; acc[i][1] += a * wv.y;
                acc[i][2] += a * wv.z; acc[i][3] += a * wv.w;
            }
        }
#pragma unroll
        for (int i = 0; i < 8; i++)
            *(float4*)&t_all[(tord * 8 + i) * 128 + tcol * 4] =
                make_float4(fmaxf(acc[i][0], 0.f), fmaxf(acc[i][1], 0.f),
                            fmaxf(acc[i][2], 0.f), fmaxf(acc[i][3], 0.f));
    }
    __syncthreads();

    {   // oe = t @ oW2 + ob2 -> comb[:,384:]
        float4 bc = *(const float4*)&ob2[tcol * 4];
        float acc[8][4];
#pragma unroll
        for (int i = 0; i < 8; i++) { acc[i][0] = bc.x; acc[i][1] = bc.y; acc[i][2] = bc.z; acc[i][3] = bc.w; }
#pragma unroll 4
        for (int k = 0; k < 128; k++) {
            float4 wv = *(const float4*)&oW2[k * 128 + tcol * 4];
#pragma unroll
            for (int i = 0; i < 8; i++) {
                float a = t_all[(tord * 8 + i) * 128 + k];
                acc[i][0] += a * wv.x; acc[i][1] += a * wv.y;
                acc[i][2] += a * wv.z; acc[i][3] += a * wv.w;
            }
        }
        __syncthreads();
#pragma unroll
        for (int i = 0; i < 8; i++)
            *(float4*)&comb[(tord * 8 + i) * 512 + 384 + tcol * 4] =
                make_float4(acc[i][0], acc[i][1], acc[i][2], acc[i][3]);
    }
    __syncthreads();

    {   // s1 = relu(comb @ sW1 + sb1)
        float4 bc = *(const float4*)&sb1[tcol * 4];
        float acc[8][4];
#pragma unroll
        for (int i = 0; i < 8; i++) { acc[i][0] = bc.x; acc[i][1] = bc.y; acc[i][2] = bc.z; acc[i][3] = bc.w; }
#pragma unroll 4
        for (int k = 0; k < 512; k++) {
            float4 wv = *(const float4*)&sW1[k * 128 + tcol * 4];
#pragma unroll
            for (int i = 0; i < 8; i++) {
                float a = comb[(tord * 8 + i) * 512 + k];
                acc[i][0] += a * wv.x; acc[i][1] += a * wv.y;
                acc[i][2] += a * wv.z; acc[i][3] += a * wv.w;
            }
        }
#pragma unroll
        for (int i = 0; i < 8; i++)
            *(float4*)&t_all[(tord * 8 + i) * 128 + tcol * 4] =
                make_float4(fmaxf(acc[i][0], 0.f), fmaxf(acc[i][1], 0.f),
                            fmaxf(acc[i][2], 0.f), fmaxf(acc[i][3], 0.f));
    }
    __syncthreads();

    {   // s2 = relu(s1 @ sW2 + sb2)
        int tc2 = tid & 15, to2 = tid >> 4;
        float4 bc = *(const float4*)&sb2[tc2 * 4];
        float acc[4][4];
#pragma unroll
        for (int i = 0; i < 4; i++) { acc[i][0] = bc.x; acc[i][1] = bc.y; acc[i][2] = bc.z; acc[i][3] = bc.w; }
#pragma unroll 4
        for (int k = 0; k < 128; k++) {
            float4 wv = *(const float4*)&sW2[k * 64 + tc2 * 4];
#pragma unroll
            for (int i = 0; i < 4; i++) {
                float a = t_all[(to2 * 4 + i) * 128 + k];
                acc[i][0] += a * wv.x; acc[i][1] += a * wv.y;
                acc[i][2] += a * wv.z; acc[i][3] += a * wv.w;
            }
        }
#pragma unroll
        for (int i = 0; i < 4; i++)
            *(float4*)&s2m[(to2 * 4 + i) * 68 + tc2 * 4] =
                make_float4(fmaxf(acc[i][0], 0.f), fmaxf(acc[i][1], 0.f),
                            fmaxf(acc[i][2], 0.f), fmaxf(acc[i][3], 0.f));
    }
    __syncthreads();

    if (tid < 32) {
        float acc = sb3[0];
#pragma unroll 8
        for (int k = 0; k < 64; k++) acc += s2m[tid * 68 + k] * sW3[k];
        out[b * 32 + tid] = acc;
    }
}

// ---------------- end-of-launch cleanup ----------------
__global__ void k_cleanup() {
    int i = blockIdx.x * blockDim.x + threadIdx.x;
    if (i <= NN) g_rowptr[i] = 0;
    if (i < NN)  g_fill[i] = 0;
}

// ---------------- launch ----------------
extern "C" void kernel_launch(void* const* d_in, const int* in_sizes, int n_in,
                              void* d_out, int out_size) {
    const float* x      = (const float*)d_in[0];
    const int*   ei     = (const int*)d_in[1];
    const float* orders = (const float*)d_in[2];
    const int*   batch  = (const int*)d_in[3];
    const float* gW1    = (const float*)d_in[4];
    const float* gb1    = (const float*)d_in[5];
    const float* gW2    = (const float*)d_in[6];
    // gb2 unused: BN cancels the second bias
    const float* gamma  = (const float*)d_in[8];
    const float* beta   = (const float*)d_in[9];
    const float* oW1    = (const float*)d_in[10];
    const float* ob1    = (const float*)d_in[11];
    const float* oW2    = (const float*)d_in[12];
    const float* ob2    = (const float*)d_in[13];
    const float* sW1    = (const float*)d_in[14];
    const float* sb1    = (const float*)d_in[15];
    const float* sW2    = (const float*)d_in[16];
    const float* sb2    = (const float*)d_in[17];
    const float* sW3    = (const float*)d_in[18];
    const float* sb3    = (const float*)d_in[19];
    float* out = (float*)d_out;

    void *p_z2, *p_wimg;
    cudaGetSymbolAddress(&p_z2,   g_z2);
    cudaGetSymbolAddress(&p_wimg, g_wimg);

    size_t head_smem = (size_t)(32 * 512 + 32 * 128 + 32 * 68 + 32 * 33) * 4;
    cudaFuncSetAttribute(k_head, cudaFuncAttributeMaxDynamicSharedMemorySize, (int)head_smem);
    cudaFuncSetAttribute(k_fgemm, cudaFuncAttributeMaxDynamicSharedMemorySize, FG_SMEM);

    k_hist<<<(NE + 255) / 256, 256>>>(ei);
    k_scan<<<1, 1024>>>();
    k_fillcsr<<<(NE + 255) / 256, 256>>>(ei);
    k_agg<0><<<(NN * 32 + 255) / 256, 256>>>(x);
    k_prepw<<<(NL * 2 * 16384 + 255) / 256, 256>>>(gW1, gW2);

    for (int l = 0; l < NL; l++) {
        if (l > 0) k_agg<1><<<(NN * 32 + 255) / 256, 256>>>((const float*)p_z2);
        k_fgemm<<<NBLK, 256, FG_SMEM>>>((const __nv_bfloat16*)p_wimg + (size_t)l * 4 * 128 * LDW,
                                        gb1 + l * HD, (float*)p_z2);
        k_stats<<<STAT_BLKS, 256>>>();
        k_finalize<<<1, 128>>>(gamma + l * HD, beta + l * HD);
    }

    k_start<<<(NN + 255) / 256, 256>>>(batch);
    k_pool<<<NB, 128>>>();
    k_head<<<NB, 128, head_smem>>>(orders, oW1, ob1, oW2, ob2,
                                   sW1, sb1, sW2, sb2, sW3, sb3, out);
    k_cleanup<<<(NN + 1 + 255) / 256, 256>>>();
}

// round 10
// speedup vs baseline: 1.2674x; 1.1033x over previous
#include <cuda_runtime.h>
#include <cuda_bf16.h>
#include <math.h>
#include <stdint.h>

#define NN 100000
#define NE 1600000
#define NB 256
#define HD 128
#define NL 3

#define NBLK 148
#define TROWS 128                      // block tile rows (8 warps x 16)
#define NT ((NN + TROWS - 1) / TROWS)  // 782
#define LDW 136                        // bf16 stride of weight tiles (272 B rows)
#define WTILE 34816                    // bytes per 128x136 bf16 weight tile

// fgemm smem map
#define STRIP_PL 4352                  // bytes per plane strip (16*136*2)
#define STRIP_SZ 8704                  // hi+lo
#define SM_A   0                       // 8 warps * 8704 = 69632
#define SM_W   69632                   // 4 tiles = 139264
#define SM_B1  (69632 + 139264)        // 512 B bias
#define FG_SMEM (SM_B1 + 512)          // 209408

// ---------------- device scratch ----------------
__device__ __align__(16) __nv_bfloat16 g_ahi[NN * HD];
__device__ __align__(16) __nv_bfloat16 g_alo[NN * HD];
__device__ float g_z2[NN * HD];
__device__ int   g_rowptr[NN + 1];
__device__ int   g_fill[NN];
__device__ int   g_colsrc[NE];
__device__ float g_stats[2 * HD];
__device__ float g_scale[HD];
__device__ float g_shift[HD];
__device__ float g_graph[NB * 3 * HD];
__device__ int   g_start[NB + 1];
__device__ __align__(16) __nv_bfloat16 g_wimg[NL * 4 * 128 * LDW];

union B4 { unsigned long long u; __nv_bfloat16 b[4]; };
union B2 { uint32_t u; __nv_bfloat16 b[2]; };

__device__ __forceinline__ uint32_t smem_u32(const void* p) {
    uint32_t a;
    asm("{ .reg .u64 t; cvta.to.shared.u64 t, %1; cvt.u32.u64 %0, t; }" : "=r"(a) : "l"(p));
    return a;
}
__device__ __forceinline__ void cp16p(uint32_t dst, const void* src, int sz) {
    asm volatile("cp.async.cg.shared.global [%0], [%1], 16, %2;" :: "r"(dst), "l"(src), "r"(sz));
}
__device__ __forceinline__ void cp_commit() { asm volatile("cp.async.commit_group;"); }
__device__ __forceinline__ void cp_wait0()  { asm volatile("cp.async.wait_group 0;"); }

__device__ __forceinline__ void ldm_x4(uint32_t* r, uint32_t addr) {
    asm volatile("ldmatrix.sync.aligned.m8n8.x4.shared.b16 {%0,%1,%2,%3}, [%4];"
                 : "=r"(r[0]), "=r"(r[1]), "=r"(r[2]), "=r"(r[3]) : "r"(addr));
}
__device__ __forceinline__ void ldm_x4t(uint32_t* r, uint32_t addr) {
    asm volatile("ldmatrix.sync.aligned.m8n8.x4.trans.shared.b16 {%0,%1,%2,%3}, [%4];"
                 : "=r"(r[0]), "=r"(r[1]), "=r"(r[2]), "=r"(r[3]) : "r"(addr));
}
__device__ __forceinline__ void mma16816(float* d, const uint32_t* a, uint32_t b0, uint32_t b1) {
    asm volatile("mma.sync.aligned.m16n8k16.row.col.f32.bf16.bf16.f32 "
                 "{%0,%1,%2,%3}, {%4,%5,%6,%7}, {%8,%9}, {%0,%1,%2,%3};"
                 : "+f"(d[0]), "+f"(d[1]), "+f"(d[2]), "+f"(d[3])
                 : "r"(a[0]), "r"(a[1]), "r"(a[2]), "r"(a[3]), "r"(b0), "r"(b1));
}

// ---------------- CSR build ----------------
__global__ void k_hist(const int* __restrict__ ei) {
    int e = blockIdx.x * blockDim.x + threadIdx.x;
    if (e < NE) atomicAdd(&g_rowptr[ei[NE + e] + 1], 1);
}

__global__ void k_scan() {
    __shared__ int wsum[32];
    __shared__ int carry;
    int tid = threadIdx.x, lane = tid & 31, wid = tid >> 5;
    if (tid == 0) carry = 0;
    const int NCH = (NN + 1 + 1023) / 1024;
    int nv = g_rowptr[tid];
    __syncthreads();
    for (int ch = 0; ch < NCH; ch++) {
        int v = nv;
        if (ch + 1 < NCH) {
            int gn = (ch + 1) * 1024 + tid;
            nv = (gn <= NN) ? g_rowptr[gn] : 0;
        }
        int x = v;
#pragma unroll
        for (int d = 1; d < 32; d <<= 1) { int y = __shfl_up_sync(0xFFFFFFFFu, x, d); if (lane >= d) x += y; }
        if (lane == 31) wsum[wid] = x;
        __syncthreads();
        if (wid == 0) {
            int y = wsum[lane];
#pragma unroll
            for (int d = 1; d < 32; d <<= 1) { int z = __shfl_up_sync(0xFFFFFFFFu, y, d); if (lane >= d) y += z; }
            wsum[lane] = y;
        }
        __syncthreads();
        if (wid > 0) x += wsum[wid - 1];
        int out = x + carry;
        int gid = ch * 1024 + tid;
        if (gid <= NN) g_rowptr[gid] = out;
        __syncthreads();
        if (tid == 1023) carry = out;
        __syncthreads();
    }
}

__global__ void k_fillcsr(const int* __restrict__ ei) {
    int e = blockIdx.x * blockDim.x + threadIdx.x;
    if (e < NE) {
        int dst = ei[NE + e];
        int pos = g_rowptr[dst] + atomicAdd(&g_fill[dst], 1);
        g_colsrc[pos] = ei[e];
    }
}

// ---------------- weight prep ([k][n] row-major, stride 136) ----------------
__global__ void k_prepw(const float* __restrict__ gW1, const float* __restrict__ gW2) {
    int idx = blockIdx.x * blockDim.x + threadIdx.x;
    if (idx >= NL * 2 * 16384) return;
    int l = idx / 32768;
    int rem = idx - l * 32768;
    int m = rem >> 14;
    int e = rem & 16383;
    int k = e >> 7;
    int n = e & 127;
    float v = (m ? gW2 : gW1)[l * 16384 + k * 128 + n];
    __nv_bfloat16 hi = __float2bfloat16_rn(v);
    __nv_bfloat16 lo = __float2bfloat16_rn(v - __bfloat162float(hi));
    __nv_bfloat16* base = g_wimg + (size_t)(l * 4 + m * 2) * 128 * LDW;
    base[k * LDW + n] = hi;
    base[128 * LDW + k * LDW + n] = lo;
}

// ---------------- aggregation ----------------
__device__ __forceinline__ float4 bnrelu4(float4 v, float4 sc, float4 sf) {
    v.x = fmaxf(v.x * sc.x + sf.x, 0.f);
    v.y = fmaxf(v.y * sc.y + sf.y, 0.f);
    v.z = fmaxf(v.z * sc.z + sf.z, 0.f);
    v.w = fmaxf(v.w * sc.w + sf.w, 0.f);
    return v;
}

template <int APPLY>
__global__ void k_agg(const float* __restrict__ src) {
    int w = (blockIdx.x * blockDim.x + threadIdx.x) >> 5;
    int lane = threadIdx.x & 31;
    if (w >= NN) return;
    float4 sc, sf;
    if (APPLY) {
        sc = *(const float4*)&g_scale[lane * 4];
        sf = *(const float4*)&g_shift[lane * 4];
    }
    const float4* hv = (const float4*)src;
    float4 self = hv[w * 32 + lane];
    float4 acc = APPLY ? bnrelu4(self, sc, sf) : self;
    int e = g_rowptr[w], eend = g_rowptr[w + 1];
    for (; e + 8 <= eend; e += 8) {
        int s[8];
#pragma unroll
        for (int j = 0; j < 8; j++) s[j] = g_colsrc[e + j];
        float4 v[8];
#pragma unroll
        for (int j = 0; j < 8; j++) v[j] = hv[s[j] * 32 + lane];
        if (APPLY) {
#pragma unroll
            for (int j = 0; j < 8; j++) v[j] = bnrelu4(v[j], sc, sf);
        }
        acc.x += ((v[0].x + v[1].x) + (v[2].x + v[3].x)) + ((v[4].x + v[5].x) + (v[6].x + v[7].x));
        acc.y += ((v[0].y + v[1].y) + (v[2].y + v[3].y)) + ((v[4].y + v[5].y) + (v[6].y + v[7].y));
        acc.z += ((v[0].z + v[1].z) + (v[2].z + v[3].z)) + ((v[4].z + v[5].z) + (v[6].z + v[7].z));
        acc.w += ((v[0].w + v[1].w) + (v[2].w + v[3].w)) + ((v[4].w + v[5].w) + (v[6].w + v[7].w));
    }
    for (; e < eend; e++) {
        int s = g_colsrc[e];
        float4 v = hv[s * 32 + lane];
        if (APPLY) v = bnrelu4(v, sc, sf);
        acc.x += v.x; acc.y += v.y; acc.z += v.z; acc.w += v.w;
    }
    float a4[4] = {acc.x, acc.y, acc.z, acc.w};
    B4 hi, lo;
#pragma unroll
    for (int e2 = 0; e2 < 4; e2++) {
        __nv_bfloat16 h = __float2bfloat16_rn(a4[e2]);
        hi.b[e2] = h;
        lo.b[e2] = __float2bfloat16_rn(a4[e2] - __bfloat162float(h));
    }
    *(unsigned long long*)&g_ahi[w * 128 + lane * 4] = hi.u;
    *(unsigned long long*)&g_alo[w * 128 + lane * 4] = lo.u;
}

// ---------------- barrier-free fused double GEMM, pipelined A-strip ----------------
__global__ void __launch_bounds__(256, 1)
k_fgemm(const __nv_bfloat16* __restrict__ wimg, const float* __restrict__ b1,
        float* __restrict__ Z2) {
    extern __shared__ char sh[];
    uint32_t sb = smem_u32(sh);
    int tid = threadIdx.x;
    int lane = tid & 31, w = tid >> 5;
    int g = lane >> 2, tg = lane & 3;

    {   // W image -> smem (8704 uint4)
        const uint4* wg = (const uint4*)wimg;
        uint4* wd = (uint4*)(sh + SM_W);
#pragma unroll
        for (int i = 0; i < 34; i++) {
            int idx = tid + i * 256;
            if (idx < 8704) wd[idx] = wg[idx];
        }
        if (tid < 128) ((float*)(sh + SM_B1))[tid] = b1[tid];
    }
    __syncthreads();

    const float* b1s = (const float*)(sh + SM_B1);
    uint32_t astrip = sb + SM_A + w * STRIP_SZ;
    uint32_t wbase = sb + SM_W;

    uint32_t a_row = lane & 15;
    uint32_t a_coff = ((lane >> 4) << 3) * 2;
    uint32_t b_row = lane & 15;
    uint32_t b_coff = ((lane >> 4) << 3) * 2;

    // prologue: prefetch first tile's strip
    {
        int row0 = blockIdx.x * TROWS + w * 16;
#pragma unroll
        for (int i = 0; i < 16; i++) {
            int idx = lane + i * 32;
            int pl = idx >> 8;
            int rem = idx & 255;
            int r = rem >> 4, ch = rem & 15;
            int gr = row0 + r;
            const __nv_bfloat16* srcp = (pl ? g_alo : g_ahi) + (size_t)gr * 128 + ch * 8;
            int sz = (gr < NN) ? 16 : 0;
            cp16p(astrip + pl * STRIP_PL + r * 272 + ch * 16, srcp, sz);
        }
        cp_commit();
    }

    for (int t = blockIdx.x; t < NT; t += NBLK) {
        int row0 = t * TROWS + w * 16;
        cp_wait0();
        __syncwarp();

        // ---- hoist ALL A fragments to registers (strip free after this) ----
        uint32_t ah[8][4], al[8][4];
#pragma unroll
        for (int kk = 0; kk < 8; kk++) {
            uint32_t aaddr = astrip + a_row * 272 + (uint32_t)(kk * 32) + a_coff;
            ldm_x4(ah[kk], aaddr);
            ldm_x4(al[kk], aaddr + STRIP_PL);
        }
        __syncwarp();

        // ---- prefetch NEXT tile's strip: overlaps GEMM1 + convert + GEMM2 ----
        int tn = t + NBLK;
        if (tn < NT) {
            int nrow0 = tn * TROWS + w * 16;
#pragma unroll
            for (int i = 0; i < 16; i++) {
                int idx = lane + i * 32;
                int pl = idx >> 8;
                int rem = idx & 255;
                int r = rem >> 4, ch = rem & 15;
                int gr = nrow0 + r;
                const __nv_bfloat16* srcp = (pl ? g_alo : g_ahi) + (size_t)gr * 128 + ch * 8;
                int sz = (gr < NN) ? 16 : 0;
                cp16p(astrip + pl * STRIP_PL + r * 272 + ch * 16, srcp, sz);
            }
            cp_commit();
        }

        // ---- GEMM1 ----
        float acc[16][4];
#pragma unroll
        for (int j = 0; j < 16; j++) { acc[j][0] = 0.f; acc[j][1] = 0.f; acc[j][2] = 0.f; acc[j][3] = 0.f; }
#pragma unroll
        for (int kk = 0; kk < 8; kk++) {
#pragma unroll
            for (int jp = 0; jp < 8; jp++) {
                uint32_t boff = b_row * 272 + (uint32_t)(kk * 16 * 272) + (uint32_t)(jp * 32) + b_coff;
                uint32_t bh[4], bl[4];
                ldm_x4t(bh, wbase + boff);
                ldm_x4t(bl, wbase + WTILE + boff);
                mma16816(acc[2 * jp],     ah[kk], bh[0], bh[1]);
                mma16816(acc[2 * jp],     ah[kk], bl[0], bl[1]);
                mma16816(acc[2 * jp],     al[kk], bh[0], bh[1]);
                mma16816(acc[2 * jp + 1], ah[kk], bh[2], bh[3]);
                mma16816(acc[2 * jp + 1], ah[kk], bl[2], bl[3]);
                mma16816(acc[2 * jp + 1], al[kk], bh[2], bh[3]);
            }
        }

        // ---- convert: z1 = relu(acc + b1) -> bf16 hi/lo A-fragments ----
        uint32_t a2h[8][4], a2l[8][4];
#pragma unroll
        for (int j2 = 0; j2 < 8; j2++) {
#pragma unroll
            for (int half = 0; half < 2; half++) {
                int tile = 2 * j2 + half;
                float bb0 = b1s[tile * 8 + 2 * tg];
                float bb1 = b1s[tile * 8 + 2 * tg + 1];
                float z0 = fmaxf(acc[tile][0] + bb0, 0.f);
                float z1 = fmaxf(acc[tile][1] + bb1, 0.f);
                float z2v = fmaxf(acc[tile][2] + bb0, 0.f);
                float z3 = fmaxf(acc[tile][3] + bb1, 0.f);
                B2 h01, h23, l01, l23;
                __nv_bfloat16 h;
                h = __float2bfloat16_rn(z0);  h01.b[0] = h; l01.b[0] = __float2bfloat16_rn(z0 - __bfloat162float(h));
                h = __float2bfloat16_rn(z1);  h01.b[1] = h; l01.b[1] = __float2bfloat16_rn(z1 - __bfloat162float(h));
                h = __float2bfloat16_rn(z2v); h23.b[0] = h; l23.b[0] = __float2bfloat16_rn(z2v - __bfloat162float(h));
                h = __float2bfloat16_rn(z3);  h23.b[1] = h; l23.b[1] = __float2bfloat16_rn(z3 - __bfloat162float(h));
                a2h[j2][2 * half]     = h01.u;
                a2h[j2][2 * half + 1] = h23.u;
                a2l[j2][2 * half]     = l01.u;
                a2l[j2][2 * half + 1] = l23.u;
            }
        }

        // ---- GEMM2 ----
        float acc2[16][4];
#pragma unroll
        for (int j = 0; j < 16; j++) { acc2[j][0] = 0.f; acc2[j][1] = 0.f; acc2[j][2] = 0.f; acc2[j][3] = 0.f; }
#pragma unroll
        for (int kk = 0; kk < 8; kk++) {
#pragma unroll
            for (int jp = 0; jp < 8; jp++) {
                uint32_t boff = b_row * 272 + (uint32_t)(kk * 16 * 272) + (uint32_t)(jp * 32) + b_coff;
                uint32_t bh[4], bl[4];
                ldm_x4t(bh, wbase + 2 * WTILE + boff);
                ldm_x4t(bl, wbase + 3 * WTILE + boff);
                mma16816(acc2[2 * jp],     a2h[kk], bh[0], bh[1]);
                mma16816(acc2[2 * jp],     a2h[kk], bl[0], bl[1]);
                mma16816(acc2[2 * jp],     a2l[kk], bh[0], bh[1]);
                mma16816(acc2[2 * jp + 1], a2h[kk], bh[2], bh[3]);
                mma16816(acc2[2 * jp + 1], a2h[kk], bl[2], bl[3]);
                mma16816(acc2[2 * jp + 1], a2l[kk], bh[2], bh[3]);
            }
        }

        // ---- z2 store ----
        int r1 = row0 + g, r2 = row0 + g + 8;
        bool l1 = r1 < NN, l2 = r2 < NN;
#pragma unroll
        for (int j = 0; j < 16; j++) {
            int col = j * 8 + 2 * tg;
            if (l1) *(float2*)&Z2[(size_t)r1 * 128 + col] = make_float2(acc2[j][0], acc2[j][1]);
            if (l2) *(float2*)&Z2[(size_t)r2 * 128 + col] = make_float2(acc2[j][2], acc2[j][3]);
        }
    }
}

// ---------------- column stats over z2raw (+ optional segment-start build) ----------------
#define STAT_BLKS 250
#define STAT_CHUNK (NN / STAT_BLKS)   // 400
__global__ void k_stats(const int* __restrict__ batch, int do_start) {
    int col = threadIdx.x & 127, half = threadIdx.x >> 7;
    int r0 = blockIdx.x * STAT_CHUNK;
    float s = 0.f, q = 0.f;
    for (int r = r0 + half; r < r0 + STAT_CHUNK; r += 2) {
        float v = g_z2[(size_t)r * 128 + col];
        s += v; q += v * v;
    }
    atomicAdd(&g_stats[col], s);
    atomicAdd(&g_stats[128 + col], q);

    if (do_start) {
        for (int n = blockIdx.x * blockDim.x + threadIdx.x; n < NN; n += gridDim.x * blockDim.x) {
            int b = batch[n];
            if (n == 0) { for (int i = 0; i <= b; i++) g_start[i] = 0; }
            else {
                int p = batch[n - 1];
                for (int i = p + 1; i <= b; i++) g_start[i] = n;
            }
            if (n == NN - 1) { for (int i = b + 1; i <= NB; i++) g_start[i] = NN; }
        }
    }
}

__global__ void k_finalize(const float* __restrict__ gamma, const float* __restrict__ beta) {
    int j = threadIdx.x;
    float mu = g_stats[j] * (1.0f / NN);
    float var = g_stats[128 + j] * (1.0f / NN) - mu * mu;
    float a = gamma[j] * rsqrtf(var + 1e-5f);
    g_scale[j] = a;
    g_shift[j] = beta[j] - mu * a;
    g_stats[j] = 0.f;
    g_stats[128 + j] = 0.f;
}

// ---------------- pooling (applies final BN) + cleanup fold-in ----------------
__global__ void k_pool() {
    int b = blockIdx.x, j = threadIdx.x;
    int s = g_start[b], e = g_start[b + 1];
    float sc = g_scale[j], sf = g_shift[j];
    float sum = 0.f, mx = -3.402823466e38f;
    int n = s;
    for (; n + 2 <= e; n += 2) {
        float v0 = g_z2[(size_t)n * HD + j] * sc + sf;
        float v1 = g_z2[(size_t)(n + 1) * HD + j] * sc + sf;
        sum += v0 + v1;
        mx = fmaxf(mx, fmaxf(v0, v1));
    }
    for (; n < e; n++) {
        float v = g_z2[(size_t)n * HD + j] * sc + sf;
        sum += v; mx = fmaxf(mx, v);
    }
    int cnt = e - s;
    g_graph[b * 384 + j]       = cnt ? sum / (float)cnt : 0.f;
    g_graph[b * 384 + 128 + j] = cnt ? mx : 0.f;
    g_graph[b * 384 + 256 + j] = sum;

    // cleanup: restore zero invariants for the next graph replay
    for (int i = b * 128 + j; i <= NN; i += NB * 128) {
        g_rowptr[i] = 0;
        if (i < NN) g_fill[i] = 0;
    }
}

// ---------------- head ----------------
__global__ void k_head(const float* __restrict__ orders,
                       const float* __restrict__ oW1, const float* __restrict__ ob1,
                       const float* __restrict__ oW2, const float* __restrict__ ob2,
                       const float* __restrict__ sW1, const float* __restrict__ sb1,
                       const float* __restrict__ sW2, const float* __restrict__ sb2,
                       const float* __restrict__ sW3, const float* __restrict__ sb3,
                       float* __restrict__ out) {
    extern __shared__ float fsh[];
    float* comb  = fsh;                      // 32*512
    float* t_all = comb + 32 * 512;          // 32*128
    float* s2m   = t_all + 32 * 128;         // 32*68
    float* ords  = s2m + 32 * 68;            // 32*33
    int b = blockIdx.x, tid = threadIdx.x;

    for (int idx = tid; idx < 32 * 384; idx += 128) {
        int o = idx / 384, k = idx - o * 384;
        comb[o * 512 + k] = g_graph[b * 384 + k];
    }
    for (int idx = tid; idx < 32 * 32; idx += 128) {
        int o = idx >> 5, k = idx & 31;
        ords[o * 33 + k] = orders[(b * 32 + o) * 32 + k];
    }
    __syncthreads();

    int tcol = tid & 31, tord = tid >> 5;

    {   // t = relu(ords @ oW1 + ob1)
        float4 bc = *(const float4*)&ob1[tcol * 4];
        float acc[8][4];
#pragma unroll
        for (int i = 0; i < 8; i++) { acc[i][0] = bc.x; acc[i][1] = bc.y; acc[i][2] = bc.z; acc[i][3] = bc.w; }
#pragma unroll
        for (int k = 0; k < 32; k++) {
            float4 wv = *(const float4*)&oW1[k * 128 + tcol * 4];
#pragma unroll
            for (int i = 0; i < 8; i++) {
                float a = ords[(tord * 8 + i) * 33 + k];
                acc[i][0] += a * wv.x; acc[i][1] += a * wv.y;
                acc[i][2] += a * wv.z; acc[i][3] += a * wv.w;
            }
        }
#pragma unroll
        for (int i = 0; i < 8; i++)
            *(float4*)&t_all[(tord * 8 + i) * 128 + tcol * 4] =
                make_float4(fmaxf(acc[i][0], 0.f), fmaxf(acc[i][1], 0.f),
                            fmaxf(acc[i][2], 0.f), fmaxf(acc[i][3], 0.f));
    }
    __syncthreads();

    {   // oe = t @ oW2 + ob2 -> comb[:,384:]
        float4 bc = *(const float4*)&ob2[tcol * 4];
        float acc[8][4];
#pragma unroll
        for (int i = 0; i < 8; i++) { acc[i][0] = bc.x; acc[i][1] = bc.y; acc[i][2] = bc.z; acc[i][3] = bc.w; }
#pragma unroll 4
        for (int k = 0; k < 128; k++) {
            float4 wv = *(const float4*)&oW2[k * 128 + tcol * 4];
#pragma unroll
            for (int i = 0; i < 8; i++) {
                float a = t_all[(tord * 8 + i) * 128 + k];
                acc[i][0] += a * wv.x; acc[i][1] += a * wv.y;
                acc[i][2] += a * wv.z; acc[i][3] += a * wv.w;
            }
        }
        __syncthreads();
#pragma unroll
        for (int i = 0; i < 8; i++)
            *(float4*)&comb[(tord * 8 + i) * 512 + 384 + tcol * 4] =
                make_float4(acc[i][0], acc[i][1], acc[i][2], acc[i][3]);
    }
    __syncthreads();

    {   // s1 = relu(comb @ sW1 + sb1)
        float4 bc = *(const float4*)&sb1[tcol * 4];
        float acc[8][4];
#pragma unroll
        for (int i = 0; i < 8; i++) { acc[i][0] = bc.x; acc[i][1] = bc.y; acc[i][2] = bc.z; acc[i][3] = bc.w; }
#pragma unroll 4
        for (int k = 0; k < 512; k++) {
            float4 wv = *(const float4*)&sW1[k * 128 + tcol * 4];
#pragma unroll
            for (int i = 0; i < 8; i++) {
                float a = comb[(tord * 8 + i) * 512 + k];
                acc[i][0] += a * wv.x; acc[i][1] += a * wv.y;
                acc[i][2] += a * wv.z; acc[i][3] += a * wv.w;
            }
        }
#pragma unroll
        for (int i = 0; i < 8; i++)
            *(float4*)&t_all[(tord * 8 + i) * 128 + tcol * 4] =
                make_float4(fmaxf(acc[i][0], 0.f), fmaxf(acc[i][1], 0.f),
                            fmaxf(acc[i][2], 0.f), fmaxf(acc[i][3], 0.f));
    }
    __syncthreads();

    {   // s2 = relu(s1 @ sW2 + sb2)
        int tc2 = tid & 15, to2 = tid >> 4;
        float4 bc = *(const float4*)&sb2[tc2 * 4];
        float acc[4][4];
#pragma unroll
        for (int i = 0; i < 4; i++) { acc[i][0] = bc.x; acc[i][1] = bc.y; acc[i][2] = bc.z; acc[i][3] = bc.w; }
#pragma unroll 4
        for (int k = 0; k < 128; k++) {
            float4 wv = *(const float4*)&sW2[k * 64 + tc2 * 4];
#pragma unroll
            for (int i = 0; i < 4; i++) {
                float a = t_all[(to2 * 4 + i) * 128 + k];
                acc[i][0] += a * wv.x; acc[i][1] += a * wv.y;
                acc[i][2] += a * wv.z; acc[i][3] += a * wv.w;
            }
        }
#pragma unroll
        for (int i = 0; i < 4; i++)
            *(float4*)&s2m[(to2 * 4 + i) * 68 + tc2 * 4] =
                make_float4(fmaxf(acc[i][0], 0.f), fmaxf(acc[i][1], 0.f),
                            fmaxf(acc[i][2], 0.f), fmaxf(acc[i][3], 0.f));
    }
    __syncthreads();

    if (tid < 32) {
        float acc = sb3[0];
#pragma unroll 8
        for (int k = 0; k < 64; k++) acc += s2m[tid * 68 + k] * sW3[k];
        out[b * 32 + tid] = acc;
    }
}

// ---------------- launch ----------------
extern "C" void kernel_launch(void* const* d_in, const int* in_sizes, int n_in,
                              void* d_out, int out_size) {
    const float* x      = (const float*)d_in[0];
    const int*   ei     = (const int*)d_in[1];
    const float* orders = (const float*)d_in[2];
    const int*   batch  = (const int*)d_in[3];
    const float* gW1    = (const float*)d_in[4];
    const float* gb1    = (const float*)d_in[5];
    const float* gW2    = (const float*)d_in[6];
    // gb2 unused: BN cancels the second bias
    const float* gamma  = (const float*)d_in[8];
    const float* beta   = (const float*)d_in[9];
    const float* oW1    = (const float*)d_in[10];
    const float* ob1    = (const float*)d_in[11];
    const float* oW2    = (const float*)d_in[12];
    const float* ob2    = (const float*)d_in[13];
    const float* sW1    = (const float*)d_in[14];
    const float* sb1    = (const float*)d_in[15];
    const float* sW2    = (const float*)d_in[16];
    const float* sb2    = (const float*)d_in[17];
    const float* sW3    = (const float*)d_in[18];
    const float* sb3    = (const float*)d_in[19];
    float* out = (float*)d_out;

    void *p_z2, *p_wimg;
    cudaGetSymbolAddress(&p_z2,   g_z2);
    cudaGetSymbolAddress(&p_wimg, g_wimg);

    size_t head_smem = (size_t)(32 * 512 + 32 * 128 + 32 * 68 + 32 * 33) * 4;
    cudaFuncSetAttribute(k_head, cudaFuncAttributeMaxDynamicSharedMemorySize, (int)head_smem);
    cudaFuncSetAttribute(k_fgemm, cudaFuncAttributeMaxDynamicSharedMemorySize, FG_SMEM);

    k_hist<<<(NE + 255) / 256, 256>>>(ei);
    k_scan<<<1, 1024>>>();
    k_fillcsr<<<(NE + 255) / 256, 256>>>(ei);
    k_agg<0><<<(NN * 32 + 255) / 256, 256>>>(x);
    k_prepw<<<(NL * 2 * 16384 + 255) / 256, 256>>>(gW1, gW2);

    for (int l = 0; l < NL; l++) {
        if (l > 0) k_agg<1><<<(NN * 32 + 255) / 256, 256>>>((const float*)p_z2);
        k_fgemm<<<NBLK, 256, FG_SMEM>>>((const __nv_bfloat16*)p_wimg + (size_t)l * 4 * 128 * LDW,
                                        gb1 + l * HD, (float*)p_z2);
        k_stats<<<STAT_BLKS, 256>>>(batch, l == NL - 1 ? 1 : 0);
        k_finalize<<<1, 128>>>(gamma + l * HD, beta + l * HD);
    }

    k_pool<<<NB, 128>>>();
    k_head<<<NB, 128, head_smem>>>(orders, oW1, ob1, oW2, ob2,
                                   sW1, sb1, sW2, sb2, sW3, sb3, out);
}